// round 2
// baseline (speedup 1.0000x reference)
#include <cuda_runtime.h>
#include <cstdint>

#define BB 64
#define TT 512
#define DD 1024
#define DKK 16
#define NEG_INF (-1e24f)

// scratch (device globals: allocation-free rule)
__device__ float g_q[BB * TT * DKK];
__device__ float g_k[BB * TT * DKK];
__device__ float g_y[(size_t)BB * TT * DD];

// ---------------------------------------------------------------------------
// K1: q = x@Wq + bq ; k = mask ? -1e24 : x@Wk + bk
// one warp per row; lane o<16 -> q[o], o>=16 -> k[o-16]
// ---------------------------------------------------------------------------
__global__ void qk_kernel(const float* __restrict__ x,
                          const unsigned char* __restrict__ maskb,
                          const float* __restrict__ Wq, const float* __restrict__ bq,
                          const float* __restrict__ Wk, const float* __restrict__ bk) {
    __shared__ float xs[8][DD];
    const int tid = threadIdx.x;
    const int r0  = blockIdx.x * 8;

    // stage 8 rows of x
    const float4* xg  = reinterpret_cast<const float4*>(x + (size_t)r0 * DD);
    float4*       xs4 = reinterpret_cast<float4*>(&xs[0][0]);
    for (int i = tid; i < 8 * DD / 4; i += 256) xs4[i] = xg[i];
    __syncthreads();

    // detect mask storage: int32 of 0/1 has zero bytes at p%4!=0; bool doesn't
    int nz = 0;
#pragma unroll
    for (int p = 0; p < 64; p++)
        if (p & 3) nz |= maskb[p];
    const bool isBool = (nz != 0);

    const int w   = tid >> 5;
    const int o   = tid & 31;
    const int row = r0 + w;
    const int oo  = o & 15;
    const float* W = (o < 16) ? Wq : Wk;
    float acc = (o < 16) ? bq[oo] : bk[oo];
    const float* xr = xs[w];

#pragma unroll 4
    for (int j = 0; j < DD; j += 4) {
        float4 xv = *reinterpret_cast<const float4*>(&xr[j]);
        acc += xv.x * W[(j + 0) * DKK + oo];
        acc += xv.y * W[(j + 1) * DKK + oo];
        acc += xv.z * W[(j + 2) * DKK + oo];
        acc += xv.w * W[(j + 3) * DKK + oo];
    }

    if (o < 16) {
        g_q[row * DKK + oo] = acc;
    } else {
        int mv = isBool ? (int)maskb[row] : reinterpret_cast<const int*>(maskb)[row];
        g_k[row * DKK + oo] = mv ? NEG_INF : acc;
    }
}

// ---------------------------------------------------------------------------
// K2: per (b, 64-query tile): scores = 4*(q@k^T), causal mask, softmax,
//     then Y = P @ x[b]  (so out = Y@Wv + bv later)
// smem: Ps[64*512] | ks[512*17] (reused as x-tile) | qs[64*16]
// ---------------------------------------------------------------------------
#define KS_STRIDE 17
#define SMEM_FLOATS (64 * 512 + 512 * KS_STRIDE + 64 * 16)

__global__ void attn_kernel(const float* __restrict__ x) {
    extern __shared__ float sm[];
    float* Ps = sm;                       // 64*512
    float* ks = sm + 64 * 512;            // 512*17 (padded)
    float* qs = ks + 512 * KS_STRIDE;     // 64*16
    float* xt = ks;                       // reuse after scores (4096 <= 8704)

    const int b    = blockIdx.y;
    const int tile = blockIdx.x;
    const int tid  = threadIdx.x;
    const int qbase = b * TT + tile * 64; // first global row of this tile

    // load k[b] (padded stride) and q tile
    for (int i = tid; i < TT * DKK; i += 256) {
        int s = i >> 4, d = i & 15;
        ks[s * KS_STRIDE + d] = g_k[(b * TT + s) * DKK + d];
    }
    for (int i = tid; i < 64 * DKK; i += 256)
        qs[i] = g_q[qbase * DKK + i];
    __syncthreads();

    // ---- scores: thread t handles row r=t>>2, cols s = (t&3)+4j ----
    {
        const int r  = tid >> 2;
        const int tq = tile * 64 + r;     // query position within sequence
        float qreg[16];
#pragma unroll
        for (int d = 0; d < 16; d++) qreg[d] = qs[r * 16 + d];
        const int s0 = tid & 3;
        for (int j = 0; j < 128; j++) {
            int s = s0 + 4 * j;
            float dot = 0.f;
#pragma unroll
            for (int d = 0; d < 16; d++) dot += qreg[d] * ks[s * KS_STRIDE + d];
            Ps[r * 512 + s] = (s > tq) ? NEG_INF : dot * 4.0f;
        }
    }
    __syncthreads();

    // ---- softmax: warp w handles rows w*8 .. w*8+7 ----
    {
        const int w = tid >> 5, l = tid & 31;
        for (int rr = 0; rr < 8; rr++) {
            const int r = w * 8 + rr;
            float v[16];
            float m = -3.4e38f;
#pragma unroll
            for (int i = 0; i < 16; i++) {
                v[i] = Ps[r * 512 + l + 32 * i];
                m = fmaxf(m, v[i]);
            }
#pragma unroll
            for (int off = 16; off > 0; off >>= 1)
                m = fmaxf(m, __shfl_xor_sync(0xffffffffu, m, off));
            float ssum = 0.f;
#pragma unroll
            for (int i = 0; i < 16; i++) { v[i] = __expf(v[i] - m); ssum += v[i]; }
#pragma unroll
            for (int off = 16; off > 0; off >>= 1)
                ssum += __shfl_xor_sync(0xffffffffu, ssum, off);
            const float inv = 1.0f / ssum;
#pragma unroll
            for (int i = 0; i < 16; i++)
                Ps[r * 512 + l + 32 * i] = v[i] * inv;
        }
    }
    __syncthreads();

    // ---- Y = P[64,512] @ x[b][512,1024], 4x8 register microtiles ----
    const int tx = tid & 15, ty = tid >> 4;
    for (int nb = 0; nb < DD; nb += 128) {
        float acc[4][8];
#pragma unroll
        for (int i = 0; i < 4; i++)
#pragma unroll
            for (int j = 0; j < 8; j++) acc[i][j] = 0.f;

        for (int k0 = 0; k0 < TT; k0 += 32) {
            __syncthreads();
            // stage x tile [32][128]
            {
                const int rr = tid >> 3;
                const int c0 = (tid & 7) * 16;
                const float4* src = reinterpret_cast<const float4*>(
                    x + (size_t)(b * TT + k0 + rr) * DD + nb + c0);
                float4* dst = reinterpret_cast<float4*>(xt + rr * 128 + c0);
#pragma unroll
                for (int q4 = 0; q4 < 4; q4++) dst[q4] = src[q4];
            }
            __syncthreads();
#pragma unroll
            for (int kk = 0; kk < 32; kk++) {
                float pf[4], xf[8];
#pragma unroll
                for (int i = 0; i < 4; i++)
                    pf[i] = Ps[(ty * 4 + i) * 512 + k0 + kk];
#pragma unroll
                for (int j = 0; j < 8; j++)
                    xf[j] = xt[kk * 128 + tx + 16 * j];
#pragma unroll
                for (int i = 0; i < 4; i++)
#pragma unroll
                    for (int j = 0; j < 8; j++)
                        acc[i][j] += pf[i] * xf[j];
            }
        }
#pragma unroll
        for (int i = 0; i < 4; i++)
#pragma unroll
            for (int j = 0; j < 8; j++)
                g_y[(size_t)(qbase + ty * 4 + i) * DD + nb + tx + 16 * j] = acc[i][j];
    }
}

// ---------------------------------------------------------------------------
// K3: out = Y @ Wv + bv   (M=32768, N=1024, K=1024)
// 128x128x16 tiles, 256 threads, 8x8 microtile
// ---------------------------------------------------------------------------
__global__ void __launch_bounds__(256, 2)
gemm_kernel(const float* __restrict__ Wv, const float* __restrict__ bv,
            float* __restrict__ out) {
    __shared__ float As[128 * 16];
    __shared__ float Bs[16 * 128];

    const int n0  = blockIdx.x * 128;
    const int m0  = blockIdx.y * 128;
    const int tid = threadIdx.x;
    const int tx  = tid & 15, ty = tid >> 4;

    float acc[8][8];
#pragma unroll
    for (int i = 0; i < 8; i++)
#pragma unroll
        for (int j = 0; j < 8; j++) acc[i][j] = 0.f;

    const int am = tid >> 1, ak = (tid & 1) * 8;   // A tile load map
    const int bk = tid >> 4, bn = (tid & 15) * 8;  // B tile load map

    for (int k0 = 0; k0 < 1024; k0 += 16) {
        float4 a0 = *reinterpret_cast<const float4*>(&g_y[(size_t)(m0 + am) * 1024 + k0 + ak]);
        float4 a1 = *reinterpret_cast<const float4*>(&g_y[(size_t)(m0 + am) * 1024 + k0 + ak + 4]);
        float4 b0 = *reinterpret_cast<const float4*>(&Wv[(size_t)(k0 + bk) * 1024 + n0 + bn]);
        float4 b1 = *reinterpret_cast<const float4*>(&Wv[(size_t)(k0 + bk) * 1024 + n0 + bn + 4]);
        __syncthreads();
        *reinterpret_cast<float4*>(&As[am * 16 + ak])     = a0;
        *reinterpret_cast<float4*>(&As[am * 16 + ak + 4]) = a1;
        *reinterpret_cast<float4*>(&Bs[bk * 128 + bn])     = b0;
        *reinterpret_cast<float4*>(&Bs[bk * 128 + bn + 4]) = b1;
        __syncthreads();
#pragma unroll
        for (int kk = 0; kk < 16; kk++) {
            float af[8], bf[8];
#pragma unroll
            for (int i = 0; i < 8; i++) af[i] = As[(ty + 16 * i) * 16 + kk];
#pragma unroll
            for (int j = 0; j < 8; j++) bf[j] = Bs[kk * 128 + tx + 16 * j];
#pragma unroll
            for (int i = 0; i < 8; i++)
#pragma unroll
                for (int j = 0; j < 8; j++) acc[i][j] += af[i] * bf[j];
        }
    }

#pragma unroll
    for (int j = 0; j < 8; j++) {
        const float bb = bv[n0 + tx + 16 * j];
#pragma unroll
        for (int i = 0; i < 8; i++)
            out[(size_t)(m0 + ty + 16 * i) * 1024 + n0 + tx + 16 * j] = acc[i][j] + bb;
    }
}

// ---------------------------------------------------------------------------
extern "C" void kernel_launch(void* const* d_in, const int* in_sizes, int n_in,
                              void* d_out, int out_size) {
    const float*         x    = (const float*)d_in[0];
    const unsigned char* mask = (const unsigned char*)d_in[1];
    const float*         Wq   = (const float*)d_in[2];
    const float*         bq   = (const float*)d_in[3];
    const float*         Wk   = (const float*)d_in[4];
    const float*         bk   = (const float*)d_in[5];
    const float*         Wv   = (const float*)d_in[6];
    const float*         bv   = (const float*)d_in[7];
    float* out = (float*)d_out;

    qk_kernel<<<BB * TT / 8, 256>>>(x, mask, Wq, bq, Wk, bk);

    const size_t smem = SMEM_FLOATS * sizeof(float);
    cudaFuncSetAttribute(attn_kernel, cudaFuncAttributeMaxDynamicSharedMemorySize, (int)smem);
    attn_kernel<<<dim3(TT / 64, BB), 256, smem>>>(x);

    gemm_kernel<<<dim3(DD / 128, BB * TT / 128), 256>>>(Wv, bv, out);
}

// round 4
// speedup vs baseline: 1.3816x; 1.3816x over previous
#include <cuda_runtime.h>
#include <cstdint>

#define BB 64
#define TT 512
#define DD 1024
#define DKK 16
#define NEG_INF (-1e24f)

// scratch (device globals: allocation-free rule)
__device__ float g_q[BB * TT * DKK];
__device__ float g_k[BB * TT * DKK];
__device__ float g_y[(size_t)BB * TT * DD];
__device__ float g_wvT[DD * DD];

// ---------------------------------------------------------------------------
// helpers
// ---------------------------------------------------------------------------
__device__ __forceinline__ uint32_t smem_u32(const void* p) {
    uint32_t a;
    asm("{ .reg .u64 t; cvta.to.shared.u64 t, %1; cvt.u32.u64 %0, t; }"
        : "=r"(a) : "l"(p));
    return a;
}
__device__ __forceinline__ float to_tf32(float x) {
    uint32_t r;
    asm("cvt.rna.tf32.f32 %0, %1;" : "=r"(r) : "f"(x));
    return __uint_as_float(r);
}

#define CP_ASYNC16(dst_u32, src_ptr) \
    asm volatile("cp.async.cg.shared.global [%0], [%1], 16;" \
                 :: "r"(dst_u32), "l"(src_ptr) : "memory")
#define CP_COMMIT() asm volatile("cp.async.commit_group;" ::: "memory")
#define CP_WAIT(n)  asm volatile("cp.async.wait_group %0;" :: "n"(n) : "memory")

__device__ __forceinline__ void mma_tf32(float* d, const uint32_t* a, const uint32_t* b) {
    asm volatile(
        "mma.sync.aligned.m16n8k8.row.col.f32.tf32.tf32.f32 "
        "{%0,%1,%2,%3}, {%4,%5,%6,%7}, {%8,%9}, {%0,%1,%2,%3};"
        : "+f"(d[0]), "+f"(d[1]), "+f"(d[2]), "+f"(d[3])
        : "r"(a[0]), "r"(a[1]), "r"(a[2]), "r"(a[3]), "r"(b[0]), "r"(b[1]));
}

// ---------------------------------------------------------------------------
// K0: WvT[n][k] = tf32(Wv[k][n])   (tiled transpose, 32x32)
// ---------------------------------------------------------------------------
__global__ void wvt_kernel(const float* __restrict__ Wv) {
    __shared__ float t[32][33];
    const int bx = blockIdx.x * 32, by = blockIdx.y * 32;
    const int tx = threadIdx.x, ty = threadIdx.y;
#pragma unroll
    for (int i = 0; i < 32; i += 8)
        t[ty + i][tx] = Wv[(size_t)(by + ty + i) * DD + bx + tx];
    __syncthreads();
#pragma unroll
    for (int i = 0; i < 32; i += 8)
        g_wvT[(size_t)(bx + ty + i) * DD + by + tx] = to_tf32(t[tx][ty + i]);
}

// ---------------------------------------------------------------------------
// K1: q = x@Wq + bq ; k = mask ? -1e24 : x@Wk + bk   (unchanged)
// ---------------------------------------------------------------------------
__global__ void qk_kernel(const float* __restrict__ x,
                          const unsigned char* __restrict__ maskb,
                          const float* __restrict__ Wq, const float* __restrict__ bq,
                          const float* __restrict__ Wk, const float* __restrict__ bk) {
    __shared__ float xs[8][DD];
    const int tid = threadIdx.x;
    const int r0  = blockIdx.x * 8;

    const float4* xg  = reinterpret_cast<const float4*>(x + (size_t)r0 * DD);
    float4*       xs4 = reinterpret_cast<float4*>(&xs[0][0]);
    for (int i = tid; i < 8 * DD / 4; i += 256) xs4[i] = xg[i];
    __syncthreads();

    int nz = 0;
#pragma unroll
    for (int p = 0; p < 64; p++)
        if (p & 3) nz |= maskb[p];
    const bool isBool = (nz != 0);

    const int w   = tid >> 5;
    const int o   = tid & 31;
    const int row = r0 + w;
    const int oo  = o & 15;
    const float* W = (o < 16) ? Wq : Wk;
    float acc = (o < 16) ? bq[oo] : bk[oo];
    const float* xr = xs[w];

#pragma unroll 4
    for (int j = 0; j < DD; j += 4) {
        float4 xv = *reinterpret_cast<const float4*>(&xr[j]);
        acc += xv.x * W[(j + 0) * DKK + oo];
        acc += xv.y * W[(j + 1) * DKK + oo];
        acc += xv.z * W[(j + 2) * DKK + oo];
        acc += xv.w * W[(j + 3) * DKK + oo];
    }

    if (o < 16) {
        g_q[row * DKK + oo] = acc;
    } else {
        int mv = isBool ? (int)maskb[row] : reinterpret_cast<const int*>(maskb)[row];
        g_k[row * DKK + oo] = mv ? NEG_INF : acc;
    }
}

// ---------------------------------------------------------------------------
// K2: scores + softmax + Y = P@x   (unchanged; g_y stores tf32-rounded)
// ---------------------------------------------------------------------------
#define KS_STRIDE 17
#define SMEM_FLOATS (64 * 512 + 512 * KS_STRIDE + 64 * 16)

__global__ void attn_kernel(const float* __restrict__ x) {
    extern __shared__ float sm[];
    float* Ps = sm;
    float* ks = sm + 64 * 512;
    float* qs = ks + 512 * KS_STRIDE;
    float* xt = ks;

    const int b    = blockIdx.y;
    const int tile = blockIdx.x;
    const int tid  = threadIdx.x;
    const int qbase = b * TT + tile * 64;

    for (int i = tid; i < TT * DKK; i += 256) {
        int s = i >> 4, d = i & 15;
        ks[s * KS_STRIDE + d] = g_k[(b * TT + s) * DKK + d];
    }
    for (int i = tid; i < 64 * DKK; i += 256)
        qs[i] = g_q[qbase * DKK + i];
    __syncthreads();

    {
        const int r  = tid >> 2;
        const int tq = tile * 64 + r;
        float qreg[16];
#pragma unroll
        for (int d = 0; d < 16; d++) qreg[d] = qs[r * 16 + d];
        const int s0 = tid & 3;
        for (int j = 0; j < 128; j++) {
            int s = s0 + 4 * j;
            float dot = 0.f;
#pragma unroll
            for (int d = 0; d < 16; d++) dot += qreg[d] * ks[s * KS_STRIDE + d];
            Ps[r * 512 + s] = (s > tq) ? NEG_INF : dot * 4.0f;
        }
    }
    __syncthreads();

    {
        const int w = tid >> 5, l = tid & 31;
        for (int rr = 0; rr < 8; rr++) {
            const int r = w * 8 + rr;
            float v[16];
            float m = -3.4e38f;
#pragma unroll
            for (int i = 0; i < 16; i++) {
                v[i] = Ps[r * 512 + l + 32 * i];
                m = fmaxf(m, v[i]);
            }
#pragma unroll
            for (int off = 16; off > 0; off >>= 1)
                m = fmaxf(m, __shfl_xor_sync(0xffffffffu, m, off));
            float ssum = 0.f;
#pragma unroll
            for (int i = 0; i < 16; i++) { v[i] = __expf(v[i] - m); ssum += v[i]; }
#pragma unroll
            for (int off = 16; off > 0; off >>= 1)
                ssum += __shfl_xor_sync(0xffffffffu, ssum, off);
            const float inv = 1.0f / ssum;
#pragma unroll
            for (int i = 0; i < 16; i++)
                Ps[r * 512 + l + 32 * i] = v[i] * inv;
        }
    }
    __syncthreads();

    const int tx = tid & 15, ty = tid >> 4;
    for (int nb = 0; nb < DD; nb += 128) {
        float acc[4][8];
#pragma unroll
        for (int i = 0; i < 4; i++)
#pragma unroll
            for (int j = 0; j < 8; j++) acc[i][j] = 0.f;

        for (int k0 = 0; k0 < TT; k0 += 32) {
            __syncthreads();
            {
                const int rr = tid >> 3;
                const int c0 = (tid & 7) * 16;
                const float4* src = reinterpret_cast<const float4*>(
                    x + (size_t)(b * TT + k0 + rr) * DD + nb + c0);
                float4* dst = reinterpret_cast<float4*>(xt + rr * 128 + c0);
#pragma unroll
                for (int q4 = 0; q4 < 4; q4++) dst[q4] = src[q4];
            }
            __syncthreads();
#pragma unroll
            for (int kk = 0; kk < 32; kk++) {
                float pf[4], xf[8];
#pragma unroll
                for (int i = 0; i < 4; i++)
                    pf[i] = Ps[(ty * 4 + i) * 512 + k0 + kk];
#pragma unroll
                for (int j = 0; j < 8; j++)
                    xf[j] = xt[kk * 128 + tx + 16 * j];
#pragma unroll
                for (int i = 0; i < 4; i++)
#pragma unroll
                    for (int j = 0; j < 8; j++)
                        acc[i][j] += pf[i] * xf[j];
            }
        }
#pragma unroll
        for (int i = 0; i < 4; i++)
#pragma unroll
            for (int j = 0; j < 8; j++)
                g_y[(size_t)(qbase + ty * 4 + i) * DD + nb + tx + 16 * j] = to_tf32(acc[i][j]);
    }
}

// ---------------------------------------------------------------------------
// K3: out = Y @ WvT^T + bv  via mma.sync tf32  (M=32768, N=1024, K=1024)
// BM=128, BN=128, BK=32, 256 thr, warp grid 2x4, 64x32/warp, cp.async x2 buf
// ---------------------------------------------------------------------------
#define BM 128
#define BN 128
#define BK 32
#define BKP 36                       // padded stride (floats)
#define TILE_FLOATS (BM * BKP)       // 4608 floats per (A or B) buffer
#define NSTAGE (DD / BK)             // 32

__global__ void __launch_bounds__(256, 2)
gemm3_mma(const float* __restrict__ bv, float* __restrict__ out) {
    extern __shared__ float sm[];
    float* As[2] = { sm,                  sm + TILE_FLOATS };
    float* Bs[2] = { sm + 2 * TILE_FLOATS, sm + 3 * TILE_FLOATS };
    const uint32_t sb = smem_u32(sm);

    const int tid  = threadIdx.x;
    const int wid  = tid >> 5, lane = tid & 31;
    const int wm   = (wid >> 2) * 64;      // warp row offset in tile
    const int wn   = (wid & 3) * 32;       // warp col offset in tile
    const int lm   = lane >> 2, lk = lane & 3;
    const int n0   = blockIdx.x * BN;
    const int m0   = blockIdx.y * BM;

    const float* Arow = g_y   + (size_t)m0 * DD;
    const float* Brow = g_wvT + (size_t)n0 * DD;

    // each thread stages 4 float4 for A and 4 for B per stage
    const int srow = tid >> 1;               // 0..127
    const int sc4  = (tid & 1) * 4;          // 0 or 4 (float4 col index)

#define PREFETCH(S, BUF) do {                                                        \
        const int k0 = (S) * BK;                                                     \
        uint32_t abase = sb + ((BUF) * TILE_FLOATS + srow * BKP + sc4 * 4) * 4;      \
        uint32_t bbase = sb + ((2 + (BUF)) * TILE_FLOATS + srow * BKP + sc4 * 4) * 4;\
        const float* asrc = Arow + (size_t)srow * DD + k0 + sc4 * 4;                 \
        const float* bsrc = Brow + (size_t)srow * DD + k0 + sc4 * 4;                 \
        _Pragma("unroll")                                                            \
        for (int q = 0; q < 4; q++) {                                                \
            CP_ASYNC16(abase + q * 16, asrc + q * 4);                                \
            CP_ASYNC16(bbase + q * 16, bsrc + q * 4);                                \
        }                                                                            \
    } while (0)

    float acc[4][4][4];
#pragma unroll
    for (int i = 0; i < 4; i++)
#pragma unroll
        for (int j = 0; j < 4; j++)
#pragma unroll
            for (int r = 0; r < 4; r++) acc[i][j][r] = 0.f;

    PREFETCH(0, 0);
    CP_COMMIT();

    for (int s = 0; s < NSTAGE; s++) {
        const int buf = s & 1;
        if (s + 1 < NSTAGE) {
            PREFETCH(s + 1, buf ^ 1);
            CP_COMMIT();
            CP_WAIT(1);
        } else {
            CP_WAIT(0);
        }
        __syncthreads();

        const float* Af = As[buf];
        const float* Bf = Bs[buf];
#pragma unroll
        for (int ksu = 0; ksu < 4; ksu++) {
            const int kb = ksu * 8;
            uint32_t a[4][4], b[4][2];
#pragma unroll
            for (int mt = 0; mt < 4; mt++) {
                const int r0 = wm + mt * 16 + lm;
                a[mt][0] = __float_as_uint(Af[r0 * BKP + kb + lk]);
                a[mt][1] = __float_as_uint(Af[(r0 + 8) * BKP + kb + lk]);
                a[mt][2] = __float_as_uint(Af[r0 * BKP + kb + lk + 4]);
                a[mt][3] = __float_as_uint(Af[(r0 + 8) * BKP + kb + lk + 4]);
            }
#pragma unroll
            for (int nt = 0; nt < 4; nt++) {
                const int c0 = wn + nt * 8 + lm;
                b[nt][0] = __float_as_uint(Bf[c0 * BKP + kb + lk]);
                b[nt][1] = __float_as_uint(Bf[c0 * BKP + kb + lk + 4]);
            }
#pragma unroll
            for (int mt = 0; mt < 4; mt++)
#pragma unroll
                for (int nt = 0; nt < 4; nt++)
                    mma_tf32(acc[mt][nt], a[mt], b[nt]);
        }
        __syncthreads();
    }
#undef PREFETCH

    // epilogue: d0,d1 -> (row, col..col+1); d2,d3 -> (row+8, col..col+1)
#pragma unroll
    for (int mt = 0; mt < 4; mt++) {
        const int row = m0 + wm + mt * 16 + lm;
#pragma unroll
        for (int nt = 0; nt < 4; nt++) {
            const int col = n0 + wn + nt * 8 + 2 * lk;
            const float b0 = bv[col], b1 = bv[col + 1];
            float2 v0 = { acc[mt][nt][0] + b0, acc[mt][nt][1] + b1 };
            float2 v1 = { acc[mt][nt][2] + b0, acc[mt][nt][3] + b1 };
            *reinterpret_cast<float2*>(out + (size_t)row * DD + col) = v0;
            *reinterpret_cast<float2*>(out + (size_t)(row + 8) * DD + col) = v1;
        }
    }
}

// ---------------------------------------------------------------------------
extern "C" void kernel_launch(void* const* d_in, const int* in_sizes, int n_in,
                              void* d_out, int out_size) {
    const float*         x    = (const float*)d_in[0];
    const unsigned char* mask = (const unsigned char*)d_in[1];
    const float*         Wq   = (const float*)d_in[2];
    const float*         bq   = (const float*)d_in[3];
    const float*         Wk   = (const float*)d_in[4];
    const float*         bk   = (const float*)d_in[5];
    const float*         Wv   = (const float*)d_in[6];
    const float*         bv   = (const float*)d_in[7];
    float* out = (float*)d_out;

    wvt_kernel<<<dim3(32, 32), dim3(32, 8)>>>(Wv);
    qk_kernel<<<BB * TT / 8, 256>>>(x, mask, Wq, bq, Wk, bk);

    const size_t smem = SMEM_FLOATS * sizeof(float);
    cudaFuncSetAttribute(attn_kernel, cudaFuncAttributeMaxDynamicSharedMemorySize, (int)smem);
    attn_kernel<<<dim3(TT / 64, BB), 256, smem>>>(x);

    const size_t gsmem = 4 * TILE_FLOATS * sizeof(float);  // 73728 B
    cudaFuncSetAttribute(gemm3_mma, cudaFuncAttributeMaxDynamicSharedMemorySize, (int)gsmem);
    gemm3_mma<<<dim3(DD / BN, BB * TT / BM), 256, gsmem>>>(bv, out);
}

// round 5
// speedup vs baseline: 2.3452x; 1.6975x over previous
#include <cuda_runtime.h>
#include <cstdint>

#define BB 64
#define TT 512
#define DD 1024
#define DKK 16
#define NEG_INF (-1e24f)

// scratch (device globals: allocation-free rule)
__device__ float g_q[BB * TT * DKK];
__device__ float g_k[BB * TT * DKK];
__device__ float g_y[(size_t)BB * TT * DD];
__device__ float g_wvT[DD * DD];
__device__ float g_xT[(size_t)BB * DD * TT];   // per-batch x^T, tf32-rounded

// ---------------------------------------------------------------------------
// helpers
// ---------------------------------------------------------------------------
__device__ __forceinline__ uint32_t smem_u32(const void* p) {
    uint32_t a;
    asm("{ .reg .u64 t; cvta.to.shared.u64 t, %1; cvt.u32.u64 %0, t; }"
        : "=r"(a) : "l"(p));
    return a;
}
__device__ __forceinline__ float to_tf32(float x) {
    uint32_t r;
    asm("cvt.rna.tf32.f32 %0, %1;" : "=r"(r) : "f"(x));
    return __uint_as_float(r);
}

#define CP_ASYNC16(dst_u32, src_ptr) \
    asm volatile("cp.async.cg.shared.global [%0], [%1], 16;" \
                 :: "r"(dst_u32), "l"(src_ptr) : "memory")
#define CP_COMMIT() asm volatile("cp.async.commit_group;" ::: "memory")
#define CP_WAIT(n)  asm volatile("cp.async.wait_group %0;" :: "n"(n) : "memory")

__device__ __forceinline__ void mma_tf32(float* d, const uint32_t* a, const uint32_t* b) {
    asm volatile(
        "mma.sync.aligned.m16n8k8.row.col.f32.tf32.tf32.f32 "
        "{%0,%1,%2,%3}, {%4,%5,%6,%7}, {%8,%9}, {%0,%1,%2,%3};"
        : "+f"(d[0]), "+f"(d[1]), "+f"(d[2]), "+f"(d[3])
        : "r"(a[0]), "r"(a[1]), "r"(a[2]), "r"(a[3]), "r"(b[0]), "r"(b[1]));
}

// ---------------------------------------------------------------------------
// K0: WvT[n][k] = tf32(Wv[k][n])
// ---------------------------------------------------------------------------
__global__ void wvt_kernel(const float* __restrict__ Wv) {
    __shared__ float t[32][33];
    const int bx = blockIdx.x * 32, by = blockIdx.y * 32;
    const int tx = threadIdx.x, ty = threadIdx.y;
#pragma unroll
    for (int i = 0; i < 32; i += 8)
        t[ty + i][tx] = Wv[(size_t)(by + ty + i) * DD + bx + tx];
    __syncthreads();
#pragma unroll
    for (int i = 0; i < 32; i += 8)
        g_wvT[(size_t)(bx + ty + i) * DD + by + tx] = to_tf32(t[tx][ty + i]);
}

// ---------------------------------------------------------------------------
// K1: q = x@Wq + bq ; k = mask ? -1e24 : x@Wk + bk ; ALSO emit xT tf32 tiles
// ---------------------------------------------------------------------------
__global__ void qk_kernel(const float* __restrict__ x,
                          const unsigned char* __restrict__ maskb,
                          const float* __restrict__ Wq, const float* __restrict__ bq,
                          const float* __restrict__ Wk, const float* __restrict__ bk) {
    __shared__ float xs[8][DD];
    const int tid = threadIdx.x;
    const int r0  = blockIdx.x * 8;

    const float4* xg  = reinterpret_cast<const float4*>(x + (size_t)r0 * DD);
    float4*       xs4 = reinterpret_cast<float4*>(&xs[0][0]);
    for (int i = tid; i < 8 * DD / 4; i += 256) xs4[i] = xg[i];
    __syncthreads();

    int nz = 0;
#pragma unroll
    for (int p = 0; p < 64; p++)
        if (p & 3) nz |= maskb[p];
    const bool isBool = (nz != 0);

    const int w   = tid >> 5;
    const int o   = tid & 31;
    const int row = r0 + w;
    const int oo  = o & 15;
    const float* W = (o < 16) ? Wq : Wk;
    float acc = (o < 16) ? bq[oo] : bk[oo];
    const float* xr = xs[w];

#pragma unroll 4
    for (int j = 0; j < DD; j += 4) {
        float4 xv = *reinterpret_cast<const float4*>(&xr[j]);
        acc += xv.x * W[(j + 0) * DKK + oo];
        acc += xv.y * W[(j + 1) * DKK + oo];
        acc += xv.z * W[(j + 2) * DKK + oo];
        acc += xv.w * W[(j + 3) * DKK + oo];
    }

    if (o < 16) {
        g_q[row * DKK + oo] = acc;
    } else {
        int mv = isBool ? (int)maskb[row] : reinterpret_cast<const int*>(maskb)[row];
        g_k[row * DKK + oo] = mv ? NEG_INF : acc;
    }

    // emit xT tf32: g_xT[b][d][s0..s0+7], full 32B sectors per d
    const int b  = r0 / TT;
    const int s0 = r0 % TT;
    float* xtb = g_xT + (size_t)b * DD * TT + s0;
#pragma unroll
    for (int i = 0; i < 4; i++) {
        const int d = tid + 256 * i;
        float4 lo, hi;
        lo.x = to_tf32(xs[0][d]); lo.y = to_tf32(xs[1][d]);
        lo.z = to_tf32(xs[2][d]); lo.w = to_tf32(xs[3][d]);
        hi.x = to_tf32(xs[4][d]); hi.y = to_tf32(xs[5][d]);
        hi.z = to_tf32(xs[6][d]); hi.w = to_tf32(xs[7][d]);
        float* dst = xtb + (size_t)d * TT;
        *reinterpret_cast<float4*>(dst)     = lo;
        *reinterpret_cast<float4*>(dst + 4) = hi;
    }
}

// ---------------------------------------------------------------------------
// K2: scores + softmax (P tf32 in smem) + Y = P@x via mma.sync tf32
// smem: Ps[64*516] | region (ks 512*17 + qs 64*16; reused as B double-buffer)
// ---------------------------------------------------------------------------
#define PST 516
#define KS_STRIDE 17
#define REGION_FLOATS (512 * KS_STRIDE + 64 * 16)     // 9728
#define BKP2 36
#define BBUF_FLOATS (128 * BKP2)                      // 4608 (x2 <= 9728)
#define ATT_SMEM_FLOATS (64 * PST + REGION_FLOATS)    // 42752

__global__ void __launch_bounds__(256, 1)
attn_kernel() {
    extern __shared__ float sm[];
    float* Ps = sm;
    float* rg = sm + 64 * PST;        // ks/qs region, later B buffers
    float* ks = rg;
    float* qs = rg + 512 * KS_STRIDE;
    const uint32_t rg_u32 = smem_u32(rg);

    const int b    = blockIdx.y;
    const int tile = blockIdx.x;
    const int tid  = threadIdx.x;
    const int qbase = b * TT + tile * 64;

    for (int i = tid; i < TT * DKK; i += 256) {
        int s = i >> 4, d = i & 15;
        ks[s * KS_STRIDE + d] = g_k[(b * TT + s) * DKK + d];
    }
    for (int i = tid; i < 64 * DKK; i += 256)
        qs[i] = g_q[qbase * DKK + i];
    __syncthreads();

    // ---- scores ----
    {
        const int r  = tid >> 2;
        const int tq = tile * 64 + r;
        float qreg[16];
#pragma unroll
        for (int d = 0; d < 16; d++) qreg[d] = qs[r * 16 + d];
        const int s0 = tid & 3;
        for (int j = 0; j < 128; j++) {
            int s = s0 + 4 * j;
            float dot = 0.f;
#pragma unroll
            for (int d = 0; d < 16; d++) dot += qreg[d] * ks[s * KS_STRIDE + d];
            Ps[r * PST + s] = (s > tq) ? NEG_INF : dot * 4.0f;
        }
    }
    __syncthreads();

    // ---- softmax (write P as tf32) ----
    {
        const int w = tid >> 5, l = tid & 31;
        for (int rr = 0; rr < 8; rr++) {
            const int r = w * 8 + rr;
            float v[16];
            float m = -3.4e38f;
#pragma unroll
            for (int i = 0; i < 16; i++) {
                v[i] = Ps[r * PST + l + 32 * i];
                m = fmaxf(m, v[i]);
            }
#pragma unroll
            for (int off = 16; off > 0; off >>= 1)
                m = fmaxf(m, __shfl_xor_sync(0xffffffffu, m, off));
            float ssum = 0.f;
#pragma unroll
            for (int i = 0; i < 16; i++) { v[i] = __expf(v[i] - m); ssum += v[i]; }
#pragma unroll
            for (int off = 16; off > 0; off >>= 1)
                ssum += __shfl_xor_sync(0xffffffffu, ssum, off);
            const float inv = 1.0f / ssum;
#pragma unroll
            for (int i = 0; i < 16; i++)
                Ps[r * PST + l + 32 * i] = to_tf32(v[i] * inv);
        }
    }
    __syncthreads();

    // ---- Y = P @ x  via mma (A = Ps tf32, B = g_xT K-major tiles) ----
    const int wid = tid >> 5, lane = tid & 31;
    const int wm = (wid >> 2) * 32;          // 0 or 32
    const int wn = (wid & 3) * 32;           // 0..96
    const int lm = lane >> 2, lk = lane & 3;
    const int srow = tid >> 1;               // 0..127
    const int sc4  = (tid & 1) * 4;

    const float* xTb = g_xT + (size_t)b * DD * TT;

    // stage st: nb = (st>>4)*128, k0 = (st&15)*32
#define PREF(ST, BUF) do {                                                           \
        const int _nb = ((ST) >> 4) * 128;                                           \
        const int _k0 = ((ST) & 15) * 32;                                            \
        uint32_t dstb = rg_u32 + ((BUF) * BBUF_FLOATS + srow * BKP2 + sc4 * 4) * 4;  \
        const float* src = xTb + (size_t)(_nb + srow) * TT + _k0 + sc4 * 4;          \
        _Pragma("unroll")                                                            \
        for (int q = 0; q < 4; q++) CP_ASYNC16(dstb + q * 16, src + q * 4);          \
    } while (0)

    float acc[2][4][4];
#pragma unroll
    for (int i = 0; i < 2; i++)
#pragma unroll
        for (int j = 0; j < 4; j++)
#pragma unroll
            for (int r = 0; r < 4; r++) acc[i][j][r] = 0.f;

    PREF(0, 0);
    CP_COMMIT();

    for (int st = 0; st < 128; st++) {
        const int buf = st & 1;
        if (st + 1 < 128) {
            PREF(st + 1, buf ^ 1);
            CP_COMMIT();
            CP_WAIT(1);
        } else {
            CP_WAIT(0);
        }
        __syncthreads();

        const float* Bf = rg + buf * BBUF_FLOATS;
        const int kbase = (st & 15) * 32;
#pragma unroll
        for (int ksu = 0; ksu < 4; ksu++) {
            const int kb = kbase + ksu * 8;
            const int kbb = ksu * 8;
            uint32_t a[2][4], bfr[4][2];
#pragma unroll
            for (int mt = 0; mt < 2; mt++) {
                const int r0 = wm + mt * 16 + lm;
                a[mt][0] = __float_as_uint(Ps[r0 * PST + kb + lk]);
                a[mt][1] = __float_as_uint(Ps[(r0 + 8) * PST + kb + lk]);
                a[mt][2] = __float_as_uint(Ps[r0 * PST + kb + lk + 4]);
                a[mt][3] = __float_as_uint(Ps[(r0 + 8) * PST + kb + lk + 4]);
            }
#pragma unroll
            for (int nt = 0; nt < 4; nt++) {
                const int c0 = wn + nt * 8 + lm;
                bfr[nt][0] = __float_as_uint(Bf[c0 * BKP2 + kbb + lk]);
                bfr[nt][1] = __float_as_uint(Bf[c0 * BKP2 + kbb + lk + 4]);
            }
#pragma unroll
            for (int mt = 0; mt < 2; mt++)
#pragma unroll
                for (int nt = 0; nt < 4; nt++)
                    mma_tf32(acc[mt][nt], a[mt], bfr[nt]);
        }
        __syncthreads();

        if ((st & 15) == 15) {
            const int nb = (st >> 4) * 128;
#pragma unroll
            for (int mt = 0; mt < 2; mt++) {
                const int row = qbase + wm + mt * 16 + lm;
#pragma unroll
                for (int nt = 0; nt < 4; nt++) {
                    const int col = nb + wn + nt * 8 + 2 * lk;
                    float2 v0 = { to_tf32(acc[mt][nt][0]), to_tf32(acc[mt][nt][1]) };
                    float2 v1 = { to_tf32(acc[mt][nt][2]), to_tf32(acc[mt][nt][3]) };
                    *reinterpret_cast<float2*>(g_y + (size_t)row * DD + col) = v0;
                    *reinterpret_cast<float2*>(g_y + (size_t)(row + 8) * DD + col) = v1;
#pragma unroll
                    for (int r = 0; r < 4; r++) acc[mt][nt][r] = 0.f;
                }
            }
        }
    }
#undef PREF
}

// ---------------------------------------------------------------------------
// K3: out = Y @ WvT^T + bv  via mma.sync tf32  (unchanged from round 4)
// ---------------------------------------------------------------------------
#define BM 128
#define BN 128
#define BK 32
#define BKP 36
#define TILE_FLOATS (BM * BKP)
#define NSTAGE (DD / BK)

__global__ void __launch_bounds__(256, 2)
gemm3_mma(const float* __restrict__ bv, float* __restrict__ out) {
    extern __shared__ float sm[];
    float* As[2] = { sm,                  sm + TILE_FLOATS };
    float* Bs[2] = { sm + 2 * TILE_FLOATS, sm + 3 * TILE_FLOATS };
    const uint32_t sb = smem_u32(sm);

    const int tid  = threadIdx.x;
    const int wid  = tid >> 5, lane = tid & 31;
    const int wm   = (wid >> 2) * 64;
    const int wn   = (wid & 3) * 32;
    const int lm   = lane >> 2, lk = lane & 3;
    const int n0   = blockIdx.x * BN;
    const int m0   = blockIdx.y * BM;

    const float* Arow = g_y   + (size_t)m0 * DD;
    const float* Brow = g_wvT + (size_t)n0 * DD;

    const int srow = tid >> 1;
    const int sc4  = (tid & 1) * 4;

#define PREFETCH(S, BUF) do {                                                        \
        const int k0 = (S) * BK;                                                     \
        uint32_t abase = sb + ((BUF) * TILE_FLOATS + srow * BKP + sc4 * 4) * 4;      \
        uint32_t bbase = sb + ((2 + (BUF)) * TILE_FLOATS + srow * BKP + sc4 * 4) * 4;\
        const float* asrc = Arow + (size_t)srow * DD + k0 + sc4 * 4;                 \
        const float* bsrc = Brow + (size_t)srow * DD + k0 + sc4 * 4;                 \
        _Pragma("unroll")                                                            \
        for (int q = 0; q < 4; q++) {                                                \
            CP_ASYNC16(abase + q * 16, asrc + q * 4);                                \
            CP_ASYNC16(bbase + q * 16, bsrc + q * 4);                                \
        }                                                                            \
    } while (0)

    float acc[4][4][4];
#pragma unroll
    for (int i = 0; i < 4; i++)
#pragma unroll
        for (int j = 0; j < 4; j++)
#pragma unroll
            for (int r = 0; r < 4; r++) acc[i][j][r] = 0.f;

    PREFETCH(0, 0);
    CP_COMMIT();

    for (int s = 0; s < NSTAGE; s++) {
        const int buf = s & 1;
        if (s + 1 < NSTAGE) {
            PREFETCH(s + 1, buf ^ 1);
            CP_COMMIT();
            CP_WAIT(1);
        } else {
            CP_WAIT(0);
        }
        __syncthreads();

        const float* Af = As[buf];
        const float* Bf = Bs[buf];
#pragma unroll
        for (int ksu = 0; ksu < 4; ksu++) {
            const int kb = ksu * 8;
            uint32_t a[4][4], b[4][2];
#pragma unroll
            for (int mt = 0; mt < 4; mt++) {
                const int r0 = wm + mt * 16 + lm;
                a[mt][0] = __float_as_uint(Af[r0 * BKP + kb + lk]);
                a[mt][1] = __float_as_uint(Af[(r0 + 8) * BKP + kb + lk]);
                a[mt][2] = __float_as_uint(Af[r0 * BKP + kb + lk + 4]);
                a[mt][3] = __float_as_uint(Af[(r0 + 8) * BKP + kb + lk + 4]);
            }
#pragma unroll
            for (int nt = 0; nt < 4; nt++) {
                const int c0 = wn + nt * 8 + lm;
                b[nt][0] = __float_as_uint(Bf[c0 * BKP + kb + lk]);
                b[nt][1] = __float_as_uint(Bf[c0 * BKP + kb + lk + 4]);
            }
#pragma unroll
            for (int mt = 0; mt < 4; mt++)
#pragma unroll
                for (int nt = 0; nt < 4; nt++)
                    mma_tf32(acc[mt][nt], a[mt], b[nt]);
        }
        __syncthreads();
    }
#undef PREFETCH

#pragma unroll
    for (int mt = 0; mt < 4; mt++) {
        const int row = m0 + wm + mt * 16 + lm;
#pragma unroll
        for (int nt = 0; nt < 4; nt++) {
            const int col = n0 + wn + nt * 8 + 2 * lk;
            const float b0 = bv[col], b1 = bv[col + 1];
            float2 v0 = { acc[mt][nt][0] + b0, acc[mt][nt][1] + b1 };
            float2 v1 = { acc[mt][nt][2] + b0, acc[mt][nt][3] + b1 };
            *reinterpret_cast<float2*>(out + (size_t)row * DD + col) = v0;
            *reinterpret_cast<float2*>(out + (size_t)(row + 8) * DD + col) = v1;
        }
    }
}

// ---------------------------------------------------------------------------
extern "C" void kernel_launch(void* const* d_in, const int* in_sizes, int n_in,
                              void* d_out, int out_size) {
    const float*         x    = (const float*)d_in[0];
    const unsigned char* mask = (const unsigned char*)d_in[1];
    const float*         Wq   = (const float*)d_in[2];
    const float*         bq   = (const float*)d_in[3];
    const float*         Wk   = (const float*)d_in[4];
    const float*         bk   = (const float*)d_in[5];
    const float*         Wv   = (const float*)d_in[6];
    const float*         bv   = (const float*)d_in[7];
    float* out = (float*)d_out;

    wvt_kernel<<<dim3(32, 32), dim3(32, 8)>>>(Wv);
    qk_kernel<<<BB * TT / 8, 256>>>(x, mask, Wq, bq, Wk, bk);

    const size_t asmem = ATT_SMEM_FLOATS * sizeof(float);
    cudaFuncSetAttribute(attn_kernel, cudaFuncAttributeMaxDynamicSharedMemorySize, (int)asmem);
    attn_kernel<<<dim3(TT / 64, BB), 256, asmem>>>();

    const size_t gsmem = 4 * TILE_FLOATS * sizeof(float);
    cudaFuncSetAttribute(gemm3_mma, cudaFuncAttributeMaxDynamicSharedMemorySize, (int)gsmem);
    gemm3_mma<<<dim3(DD / BN, BB * TT / BM), 256, gsmem>>>(bv, out);
}

// round 6
// speedup vs baseline: 2.5018x; 1.0668x over previous
#include <cuda_runtime.h>
#include <cstdint>

#define BB 64
#define TT 512
#define DD 1024
#define DKK 16
#define NEG_INF (-1e24f)

// scratch (device globals: allocation-free rule)
__device__ float g_q[BB * TT * DKK];
__device__ float g_k[BB * TT * DKK];
__device__ float g_y[(size_t)BB * TT * DD];
__device__ float g_wvT[DD * DD];
__device__ float g_xT[(size_t)BB * DD * TT];   // per-batch x^T, tf32-rounded

// ---------------------------------------------------------------------------
// helpers
// ---------------------------------------------------------------------------
__device__ __forceinline__ uint32_t smem_u32(const void* p) {
    uint32_t a;
    asm("{ .reg .u64 t; cvta.to.shared.u64 t, %1; cvt.u32.u64 %0, t; }"
        : "=r"(a) : "l"(p));
    return a;
}
__device__ __forceinline__ float to_tf32(float x) {
    uint32_t r;
    asm("cvt.rna.tf32.f32 %0, %1;" : "=r"(r) : "f"(x));
    return __uint_as_float(r);
}

#define CP_ASYNC16(dst_u32, src_ptr) \
    asm volatile("cp.async.cg.shared.global [%0], [%1], 16;" \
                 :: "r"(dst_u32), "l"(src_ptr) : "memory")
#define CP_COMMIT() asm volatile("cp.async.commit_group;" ::: "memory")
#define CP_WAIT(n)  asm volatile("cp.async.wait_group %0;" :: "n"(n) : "memory")

__device__ __forceinline__ void mma_tf32(float* d, const uint32_t* a, const uint32_t* b) {
    asm volatile(
        "mma.sync.aligned.m16n8k8.row.col.f32.tf32.tf32.f32 "
        "{%0,%1,%2,%3}, {%4,%5,%6,%7}, {%8,%9}, {%0,%1,%2,%3};"
        : "+f"(d[0]), "+f"(d[1]), "+f"(d[2]), "+f"(d[3])
        : "r"(a[0]), "r"(a[1]), "r"(a[2]), "r"(a[3]), "r"(b[0]), "r"(b[1]));
}

// ldmatrix: 8x8 b16 matrices == 8x4 fp32 tiles; lane -> (row l>>2, f32col l&3)
#define LDSM_X4(r0, r1, r2, r3, addr) \
    asm volatile("ldmatrix.sync.aligned.m8n8.x4.shared.b16 {%0,%1,%2,%3}, [%4];" \
                 : "=r"(r0), "=r"(r1), "=r"(r2), "=r"(r3) : "r"(addr))
#define LDSM_X2(r0, r1, addr) \
    asm volatile("ldmatrix.sync.aligned.m8n8.x2.shared.b16 {%0,%1}, [%2];" \
                 : "=r"(r0), "=r"(r1) : "r"(addr))

// ---------------------------------------------------------------------------
// K0: WvT[n][k] = tf32(Wv[k][n])
// ---------------------------------------------------------------------------
__global__ void wvt_kernel(const float* __restrict__ Wv) {
    __shared__ float t[32][33];
    const int bx = blockIdx.x * 32, by = blockIdx.y * 32;
    const int tx = threadIdx.x, ty = threadIdx.y;
#pragma unroll
    for (int i = 0; i < 32; i += 8)
        t[ty + i][tx] = Wv[(size_t)(by + ty + i) * DD + bx + tx];
    __syncthreads();
#pragma unroll
    for (int i = 0; i < 32; i += 8)
        g_wvT[(size_t)(bx + ty + i) * DD + by + tx] = to_tf32(t[tx][ty + i]);
}

// ---------------------------------------------------------------------------
// K1: q = x@Wq + bq ; k = mask ? -1e24 : x@Wk + bk ; ALSO emit xT tf32 tiles
// ---------------------------------------------------------------------------
__global__ void qk_kernel(const float* __restrict__ x,
                          const unsigned char* __restrict__ maskb,
                          const float* __restrict__ Wq, const float* __restrict__ bq,
                          const float* __restrict__ Wk, const float* __restrict__ bk) {
    __shared__ float xs[8][DD];
    const int tid = threadIdx.x;
    const int r0  = blockIdx.x * 8;

    const float4* xg  = reinterpret_cast<const float4*>(x + (size_t)r0 * DD);
    float4*       xs4 = reinterpret_cast<float4*>(&xs[0][0]);
    for (int i = tid; i < 8 * DD / 4; i += 256) xs4[i] = xg[i];
    __syncthreads();

    int nz = 0;
#pragma unroll
    for (int p = 0; p < 64; p++)
        if (p & 3) nz |= maskb[p];
    const bool isBool = (nz != 0);

    const int w   = tid >> 5;
    const int o   = tid & 31;
    const int row = r0 + w;
    const int oo  = o & 15;
    const float* W = (o < 16) ? Wq : Wk;
    float acc = (o < 16) ? bq[oo] : bk[oo];
    const float* xr = xs[w];

#pragma unroll 4
    for (int j = 0; j < DD; j += 4) {
        float4 xv = *reinterpret_cast<const float4*>(&xr[j]);
        acc += xv.x * W[(j + 0) * DKK + oo];
        acc += xv.y * W[(j + 1) * DKK + oo];
        acc += xv.z * W[(j + 2) * DKK + oo];
        acc += xv.w * W[(j + 3) * DKK + oo];
    }

    if (o < 16) {
        g_q[row * DKK + oo] = acc;
    } else {
        int mv = isBool ? (int)maskb[row] : reinterpret_cast<const int*>(maskb)[row];
        g_k[row * DKK + oo] = mv ? NEG_INF : acc;
    }

    // emit xT tf32: g_xT[b][d][s0..s0+7], full 32B sectors per d
    const int b  = r0 / TT;
    const int s0 = r0 % TT;
    float* xtb = g_xT + (size_t)b * DD * TT + s0;
#pragma unroll
    for (int i = 0; i < 4; i++) {
        const int d = tid + 256 * i;
        float4 lo, hi;
        lo.x = to_tf32(xs[0][d]); lo.y = to_tf32(xs[1][d]);
        lo.z = to_tf32(xs[2][d]); lo.w = to_tf32(xs[3][d]);
        hi.x = to_tf32(xs[4][d]); hi.y = to_tf32(xs[5][d]);
        hi.z = to_tf32(xs[6][d]); hi.w = to_tf32(xs[7][d]);
        float* dst = xtb + (size_t)d * TT;
        *reinterpret_cast<float4*>(dst)     = lo;
        *reinterpret_cast<float4*>(dst + 4) = hi;
    }
}

// ---------------------------------------------------------------------------
// K2: scores + softmax (P tf32 in smem) + Y = P@x via mma.sync + ldmatrix
// ---------------------------------------------------------------------------
#define PST 516
#define KS_STRIDE 17
#define REGION_FLOATS (512 * KS_STRIDE + 64 * 16)     // 9728
#define BKP2 36
#define BBUF_FLOATS (128 * BKP2)                      // 4608 (x2 <= 9728)
#define ATT_SMEM_FLOATS (64 * PST + REGION_FLOATS)    // 42752

__global__ void __launch_bounds__(256, 1)
attn_kernel() {
    extern __shared__ float sm[];
    float* Ps = sm;
    float* rg = sm + 64 * PST;        // ks/qs region, later B buffers
    float* ks = rg;
    float* qs = rg + 512 * KS_STRIDE;
    const uint32_t ps_u32 = smem_u32(sm);
    const uint32_t rg_u32 = smem_u32(rg);

    const int b    = blockIdx.y;
    const int tile = blockIdx.x;
    const int tid  = threadIdx.x;
    const int qbase = b * TT + tile * 64;

    for (int i = tid; i < TT * DKK; i += 256) {
        int s = i >> 4, d = i & 15;
        ks[s * KS_STRIDE + d] = g_k[(b * TT + s) * DKK + d];
    }
    for (int i = tid; i < 64 * DKK; i += 256)
        qs[i] = g_q[qbase * DKK + i];
    __syncthreads();

    // ---- scores ----
    {
        const int r  = tid >> 2;
        const int tq = tile * 64 + r;
        float qreg[16];
#pragma unroll
        for (int d = 0; d < 16; d++) qreg[d] = qs[r * 16 + d];
        const int s0 = tid & 3;
        for (int j = 0; j < 128; j++) {
            int s = s0 + 4 * j;
            float dot = 0.f;
#pragma unroll
            for (int d = 0; d < 16; d++) dot += qreg[d] * ks[s * KS_STRIDE + d];
            Ps[r * PST + s] = (s > tq) ? NEG_INF : dot * 4.0f;
        }
    }
    __syncthreads();

    // ---- softmax (write P as tf32) ----
    {
        const int w = tid >> 5, l = tid & 31;
        for (int rr = 0; rr < 8; rr++) {
            const int r = w * 8 + rr;
            float v[16];
            float m = -3.4e38f;
#pragma unroll
            for (int i = 0; i < 16; i++) {
                v[i] = Ps[r * PST + l + 32 * i];
                m = fmaxf(m, v[i]);
            }
#pragma unroll
            for (int off = 16; off > 0; off >>= 1)
                m = fmaxf(m, __shfl_xor_sync(0xffffffffu, m, off));
            float ssum = 0.f;
#pragma unroll
            for (int i = 0; i < 16; i++) { v[i] = __expf(v[i] - m); ssum += v[i]; }
#pragma unroll
            for (int off = 16; off > 0; off >>= 1)
                ssum += __shfl_xor_sync(0xffffffffu, ssum, off);
            const float inv = 1.0f / ssum;
#pragma unroll
            for (int i = 0; i < 16; i++)
                Ps[r * PST + l + 32 * i] = to_tf32(v[i] * inv);
        }
    }
    __syncthreads();

    // ---- Y = P @ x  via mma + ldmatrix ----
    const int wid = tid >> 5, lane = tid & 31;
    const int wm = (wid >> 2) * 32;          // 0 or 32
    const int wn = (wid & 3) * 32;           // 0..96
    const int lm = lane >> 2, lk = lane & 3;
    const int srow = tid >> 1;               // 0..127
    const int sc4  = (tid & 1) * 4;

    // ldmatrix lane address components
    const int lr  = lane & 7;
    const int ah  = (lane >> 3) & 1;         // row half (for x4)
    const int ac  = lane >> 4;               // col half (for x4)
    // A base (Ps): row = wm + ah*8 + lr, col = ac*4  (add mt*16*PST, kb)
    const uint32_t aAddr0 = ps_u32 + ((wm + ah * 8 + lr) * PST + ac * 4) * 4;
    // B base (rg buf): row = wn + (lane&15? lanes0-15 used): row = wn + lr, col = ah*4
    const uint32_t bAddr0 = rg_u32 + ((wn + lr) * BKP2 + ah * 4) * 4;

    const float* xTb = g_xT + (size_t)b * DD * TT;

#define PREF(ST, BUF) do {                                                           \
        const int _nb = ((ST) >> 4) * 128;                                           \
        const int _k0 = ((ST) & 15) * 32;                                            \
        uint32_t dstb = rg_u32 + ((BUF) * BBUF_FLOATS + srow * BKP2 + sc4 * 4) * 4;  \
        const float* src = xTb + (size_t)(_nb + srow) * TT + _k0 + sc4 * 4;          \
        _Pragma("unroll")                                                            \
        for (int q = 0; q < 4; q++) CP_ASYNC16(dstb + q * 16, src + q * 4);          \
    } while (0)

    float acc[2][4][4];
#pragma unroll
    for (int i = 0; i < 2; i++)
#pragma unroll
        for (int j = 0; j < 4; j++)
#pragma unroll
            for (int r = 0; r < 4; r++) acc[i][j][r] = 0.f;

    PREF(0, 0);
    CP_COMMIT();

    for (int st = 0; st < 128; st++) {
        const int buf = st & 1;
        if (st + 1 < 128) {
            PREF(st + 1, buf ^ 1);
            CP_COMMIT();
            CP_WAIT(1);
        } else {
            CP_WAIT(0);
        }
        __syncthreads();

        const uint32_t bBuf = bAddr0 + buf * BBUF_FLOATS * 4;
        const int kbase = (st & 15) * 32;
#pragma unroll
        for (int ksu = 0; ksu < 4; ksu++) {
            const int kb = kbase + ksu * 8;
            uint32_t a[2][4], bfr[4][2];
#pragma unroll
            for (int mt = 0; mt < 2; mt++)
                LDSM_X4(a[mt][0], a[mt][1], a[mt][2], a[mt][3],
                        aAddr0 + (mt * 16 * PST + kb) * 4);
#pragma unroll
            for (int nt = 0; nt < 4; nt++)
                LDSM_X2(bfr[nt][0], bfr[nt][1],
                        bBuf + (nt * 8 * BKP2 + ksu * 8) * 4);
#pragma unroll
            for (int mt = 0; mt < 2; mt++)
#pragma unroll
                for (int nt = 0; nt < 4; nt++)
                    mma_tf32(acc[mt][nt], a[mt], bfr[nt]);
        }
        __syncthreads();

        if ((st & 15) == 15) {
            const int nb = (st >> 4) * 128;
#pragma unroll
            for (int mt = 0; mt < 2; mt++) {
                const int row = qbase + wm + mt * 16 + lm;
#pragma unroll
                for (int nt = 0; nt < 4; nt++) {
                    const int col = nb + wn + nt * 8 + 2 * lk;
                    float2 v0 = { to_tf32(acc[mt][nt][0]), to_tf32(acc[mt][nt][1]) };
                    float2 v1 = { to_tf32(acc[mt][nt][2]), to_tf32(acc[mt][nt][3]) };
                    *reinterpret_cast<float2*>(g_y + (size_t)row * DD + col) = v0;
                    *reinterpret_cast<float2*>(g_y + (size_t)(row + 8) * DD + col) = v1;
#pragma unroll
                    for (int r = 0; r < 4; r++) acc[mt][nt][r] = 0.f;
                }
            }
        }
    }
#undef PREF
}

// ---------------------------------------------------------------------------
// K3: out = Y @ WvT^T + bv  via mma.sync + ldmatrix
// ---------------------------------------------------------------------------
#define BM 128
#define BN 128
#define BK 32
#define BKP 36
#define TILE_FLOATS (BM * BKP)
#define NSTAGE (DD / BK)

__global__ void __launch_bounds__(256, 2)
gemm3_mma(const float* __restrict__ bv, float* __restrict__ out) {
    extern __shared__ float sm[];
    const uint32_t sb = smem_u32(sm);

    const int tid  = threadIdx.x;
    const int wid  = tid >> 5, lane = tid & 31;
    const int wm   = (wid >> 2) * 64;
    const int wn   = (wid & 3) * 32;
    const int lm   = lane >> 2, lk = lane & 3;
    const int n0   = blockIdx.x * BN;
    const int m0   = blockIdx.y * BM;

    const float* Arow = g_y   + (size_t)m0 * DD;
    const float* Brow = g_wvT + (size_t)n0 * DD;

    const int srow = tid >> 1;
    const int sc4  = (tid & 1) * 4;

    const int lr = lane & 7;
    const int ah = (lane >> 3) & 1;
    const int ac = lane >> 4;
    const uint32_t aAddr0 = sb + ((wm + ah * 8 + lr) * BKP + ac * 4) * 4;
    const uint32_t bAddr0 = sb + 2 * TILE_FLOATS * 4 + ((wn + lr) * BKP + ah * 4) * 4;

#define PREFETCH(S, BUF) do {                                                        \
        const int k0 = (S) * BK;                                                     \
        uint32_t abase = sb + ((BUF) * TILE_FLOATS + srow * BKP + sc4 * 4) * 4;      \
        uint32_t bbase = sb + ((2 + (BUF)) * TILE_FLOATS + srow * BKP + sc4 * 4) * 4;\
        const float* asrc = Arow + (size_t)srow * DD + k0 + sc4 * 4;                 \
        const float* bsrc = Brow + (size_t)srow * DD + k0 + sc4 * 4;                 \
        _Pragma("unroll")                                                            \
        for (int q = 0; q < 4; q++) {                                                \
            CP_ASYNC16(abase + q * 16, asrc + q * 4);                                \
            CP_ASYNC16(bbase + q * 16, bsrc + q * 4);                                \
        }                                                                            \
    } while (0)

    float acc[4][4][4];
#pragma unroll
    for (int i = 0; i < 4; i++)
#pragma unroll
        for (int j = 0; j < 4; j++)
#pragma unroll
            for (int r = 0; r < 4; r++) acc[i][j][r] = 0.f;

    PREFETCH(0, 0);
    CP_COMMIT();

    for (int s = 0; s < NSTAGE; s++) {
        const int buf = s & 1;
        if (s + 1 < NSTAGE) {
            PREFETCH(s + 1, buf ^ 1);
            CP_COMMIT();
            CP_WAIT(1);
        } else {
            CP_WAIT(0);
        }
        __syncthreads();

        const uint32_t aBuf = aAddr0 + buf * TILE_FLOATS * 4;
        const uint32_t bBuf = bAddr0 + buf * TILE_FLOATS * 4;
#pragma unroll
        for (int ksu = 0; ksu < 4; ksu++) {
            uint32_t a[4][4], b[4][2];
#pragma unroll
            for (int mt = 0; mt < 4; mt++)
                LDSM_X4(a[mt][0], a[mt][1], a[mt][2], a[mt][3],
                        aBuf + (mt * 16 * BKP + ksu * 8) * 4);
#pragma unroll
            for (int nt = 0; nt < 4; nt++)
                LDSM_X2(b[nt][0], b[nt][1],
                        bBuf + (nt * 8 * BKP + ksu * 8) * 4);
#pragma unroll
            for (int mt = 0; mt < 4; mt++)
#pragma unroll
                for (int nt = 0; nt < 4; nt++)
                    mma_tf32(acc[mt][nt], a[mt], b[nt]);
        }
        __syncthreads();
    }
#undef PREFETCH

#pragma unroll
    for (int mt = 0; mt < 4; mt++) {
        const int row = m0 + wm + mt * 16 + lm;
#pragma unroll
        for (int nt = 0; nt < 4; nt++) {
            const int col = n0 + wn + nt * 8 + 2 * lk;
            const float b0 = bv[col], b1 = bv[col + 1];
            float2 v0 = { acc[mt][nt][0] + b0, acc[mt][nt][1] + b1 };
            float2 v1 = { acc[mt][nt][2] + b0, acc[mt][nt][3] + b1 };
            *reinterpret_cast<float2*>(out + (size_t)row * DD + col) = v0;
            *reinterpret_cast<float2*>(out + (size_t)(row + 8) * DD + col) = v1;
        }
    }
}

// ---------------------------------------------------------------------------
extern "C" void kernel_launch(void* const* d_in, const int* in_sizes, int n_in,
                              void* d_out, int out_size) {
    const float*         x    = (const float*)d_in[0];
    const unsigned char* mask = (const unsigned char*)d_in[1];
    const float*         Wq   = (const float*)d_in[2];
    const float*         bq   = (const float*)d_in[3];
    const float*         Wk   = (const float*)d_in[4];
    const float*         bk   = (const float*)d_in[5];
    const float*         Wv   = (const float*)d_in[6];
    const float*         bv   = (const float*)d_in[7];
    float* out = (float*)d_out;

    wvt_kernel<<<dim3(32, 32), dim3(32, 8)>>>(Wv);
    qk_kernel<<<BB * TT / 8, 256>>>(x, mask, Wq, bq, Wk, bk);

    const size_t asmem = ATT_SMEM_FLOATS * sizeof(float);
    cudaFuncSetAttribute(attn_kernel, cudaFuncAttributeMaxDynamicSharedMemorySize, (int)asmem);
    attn_kernel<<<dim3(TT / 64, BB), 256, asmem>>>();

    const size_t gsmem = 4 * TILE_FLOATS * sizeof(float);
    cudaFuncSetAttribute(gemm3_mma, cudaFuncAttributeMaxDynamicSharedMemorySize, (int)gsmem);
    gemm3_mma<<<dim3(DD / BN, BB * TT / BM), 256, gsmem>>>(bv, out);
}

// round 9
// speedup vs baseline: 3.0489x; 1.2187x over previous
#include <cuda_runtime.h>
#include <cstdint>

#define BB 64
#define TT 512
#define DD 1024
#define DKK 16
#define NEG_INF (-1e24f)

// scratch (device globals: allocation-free rule)
__device__ float g_q[BB * TT * DKK];
__device__ float g_k[BB * TT * DKK];
__device__ float g_y[(size_t)BB * TT * DD];
__device__ float g_wvT[DD * DD];
__device__ float g_xT[(size_t)BB * DD * TT];   // per-batch x^T, tf32-rounded

// ---------------------------------------------------------------------------
// helpers
// ---------------------------------------------------------------------------
__device__ __forceinline__ uint32_t smem_u32(const void* p) {
    uint32_t a;
    asm("{ .reg .u64 t; cvta.to.shared.u64 t, %1; cvt.u32.u64 %0, t; }"
        : "=r"(a) : "l"(p));
    return a;
}
__device__ __forceinline__ float to_tf32(float x) {
    uint32_t r;
    asm("cvt.rna.tf32.f32 %0, %1;" : "=r"(r) : "f"(x));
    return __uint_as_float(r);
}

#define CP_ASYNC16(dst_u32, src_ptr) \
    asm volatile("cp.async.cg.shared.global [%0], [%1], 16;" \
                 :: "r"(dst_u32), "l"(src_ptr) : "memory")
#define CP_COMMIT() asm volatile("cp.async.commit_group;" ::: "memory")
#define CP_WAIT(n)  asm volatile("cp.async.wait_group %0;" :: "n"(n) : "memory")

__device__ __forceinline__ void mma_tf32(float* d, const uint32_t* a, const uint32_t* b) {
    asm volatile(
        "mma.sync.aligned.m16n8k8.row.col.f32.tf32.tf32.f32 "
        "{%0,%1,%2,%3}, {%4,%5,%6,%7}, {%8,%9}, {%0,%1,%2,%3};"
        : "+f"(d[0]), "+f"(d[1]), "+f"(d[2]), "+f"(d[3])
        : "r"(a[0]), "r"(a[1]), "r"(a[2]), "r"(a[3]), "r"(b[0]), "r"(b[1]));
}

// ldmatrix: 8x8 b16 matrices == 8x4 fp32 tiles; lane -> (row l>>2, f32col l&3)
#define LDSM_X4(r0, r1, r2, r3, addr) \
    asm volatile("ldmatrix.sync.aligned.m8n8.x4.shared.b16 {%0,%1,%2,%3}, [%4];" \
                 : "=r"(r0), "=r"(r1), "=r"(r2), "=r"(r3) : "r"(addr))
#define LDSM_X2(r0, r1, addr) \
    asm volatile("ldmatrix.sync.aligned.m8n8.x2.shared.b16 {%0,%1}, [%2];" \
                 : "=r"(r0), "=r"(r1) : "r"(addr))

// ---------------------------------------------------------------------------
// K0: WvT[n][k] = tf32(Wv[k][n])
// ---------------------------------------------------------------------------
__global__ void wvt_kernel(const float* __restrict__ Wv) {
    __shared__ float t[32][33];
    const int bx = blockIdx.x * 32, by = blockIdx.y * 32;
    const int tx = threadIdx.x, ty = threadIdx.y;
#pragma unroll
    for (int i = 0; i < 32; i += 8)
        t[ty + i][tx] = Wv[(size_t)(by + ty + i) * DD + bx + tx];
    __syncthreads();
#pragma unroll
    for (int i = 0; i < 32; i += 8)
        g_wvT[(size_t)(bx + ty + i) * DD + by + tx] = to_tf32(t[tx][ty + i]);
}

// ---------------------------------------------------------------------------
// K1 v2: smem-GEMM qk + fused xT emission.
// Block: 128 rows x 32 cols (q0..15 | k0..15), Kc=64, 16 chunks.
// QKPAD=68: row stride 272 B (16-aligned for cp.async), 68%32=4 -> no conflicts
// ---------------------------------------------------------------------------
#define QKR 128
#define QKC 64
#define QKPAD 68

__global__ void __launch_bounds__(256, 2)
qk_kernel(const float* __restrict__ x,
          const unsigned char* __restrict__ maskb,
          const float* __restrict__ Wq, const float* __restrict__ bq,
          const float* __restrict__ Wk, const float* __restrict__ bk) {
    __shared__ float xs[QKR * QKPAD];
    __shared__ float ws[QKC * 32];
    const uint32_t xs_u32 = smem_u32(xs);
    const uint32_t ws_u32 = smem_u32(ws);

    const int tid = threadIdx.x;
    const int r0  = blockIdx.x * QKR;
    const int b   = r0 / TT;
    const int sl0 = r0 % TT;

    const int tr = tid >> 3, tc = tid & 7;

    float acc[4][4];
#pragma unroll
    for (int j = 0; j < 4; j++) {
        const int c = tc * 4 + j;
        const float bias = (c < 16) ? bq[c] : bk[c - 16];
#pragma unroll
        for (int i = 0; i < 4; i++) acc[i][j] = bias;
    }

    // xT emission map: d = tid>>2 (0..63), sseg = (tid&3)*32
    const int ed   = tid >> 2;
    const int eseg = (tid & 3) * 32;

    for (int ch = 0; ch < 16; ch++) {
        const int k0 = ch * QKC;

        // stage W: ws[kk][0..15]=Wq[k0+kk][:], ws[kk][16..31]=Wk[k0+kk][:]
        // 64 rows x 4 float4 per matrix == 256 float4 == exactly one pass
        {
            const int kk = tid >> 2, c4 = tid & 3;   // kk in 0..63
            CP_ASYNC16(ws_u32 + (kk * 32 + c4 * 4) * 4,
                       Wq + (size_t)(k0 + kk) * DKK + c4 * 4);
            CP_ASYNC16(ws_u32 + (kk * 32 + 16 + c4 * 4) * 4,
                       Wk + (size_t)(k0 + kk) * DKK + c4 * 4);
        }
        // stage x tile [128][64]
#pragma unroll
        for (int it = 0; it < 8; it++) {
            const int idx = tid + it * 256;     // 0..2047 float4s
            const int row = idx >> 4, c4 = idx & 15;
            CP_ASYNC16(xs_u32 + (row * QKPAD + c4 * 4) * 4,
                       x + (size_t)(r0 + row) * DD + k0 + c4 * 4);
        }
        CP_COMMIT();
        CP_WAIT(0);
        __syncthreads();

        // compute
#pragma unroll 4
        for (int kk = 0; kk < QKC; kk++) {
            float a[4];
#pragma unroll
            for (int i = 0; i < 4; i++) a[i] = xs[(tr * 4 + i) * QKPAD + kk];
            const float4 w = *reinterpret_cast<const float4*>(&ws[kk * 32 + tc * 4]);
#pragma unroll
            for (int i = 0; i < 4; i++) {
                acc[i][0] += a[i] * w.x;
                acc[i][1] += a[i] * w.y;
                acc[i][2] += a[i] * w.z;
                acc[i][3] += a[i] * w.w;
            }
        }

        // emit xT tf32 for dims k0..k0+63, s = sl0..sl0+127
        {
            float* dst = g_xT + (size_t)b * DD * TT + (size_t)(k0 + ed) * TT + sl0 + eseg;
#pragma unroll
            for (int j = 0; j < 8; j++) {
                float4 v;
                v.x = to_tf32(xs[(eseg + 4 * j + 0) * QKPAD + ed]);
                v.y = to_tf32(xs[(eseg + 4 * j + 1) * QKPAD + ed]);
                v.z = to_tf32(xs[(eseg + 4 * j + 2) * QKPAD + ed]);
                v.w = to_tf32(xs[(eseg + 4 * j + 3) * QKPAD + ed]);
                *reinterpret_cast<float4*>(dst + 4 * j) = v;
            }
        }
        __syncthreads();
    }

    // mask storage detect: int32 of 0/1 has zero bytes at p%4!=0
    int nz = 0;
#pragma unroll
    for (int p = 0; p < 64; p++)
        if (p & 3) nz |= maskb[p];
    const bool isBool = (nz != 0);

#pragma unroll
    for (int i = 0; i < 4; i++) {
        const int row = r0 + tr * 4 + i;
        const int mv = isBool ? (int)maskb[row]
                              : reinterpret_cast<const int*>(maskb)[row];
#pragma unroll
        for (int j = 0; j < 4; j++) {
            const int c = tc * 4 + j;
            if (c < 16) g_q[row * DKK + c] = acc[i][j];
            else        g_k[row * DKK + (c - 16)] = mv ? NEG_INF : acc[i][j];
        }
    }
}

// ---------------------------------------------------------------------------
// K2: scores + softmax (P tf32 in smem) + Y = P@x via mma + ldmatrix, 3-stage
// ---------------------------------------------------------------------------
#define PST 516
#define KS_STRIDE 17
#define BKP2 36
#define BBUF_FLOATS (128 * BKP2)                      // 4608
#define REGION_FLOATS (3 * BBUF_FLOATS)               // 13824 (>= ks+qs 9728)
#define ATT_SMEM_FLOATS (64 * PST + REGION_FLOATS)    // 46848

__global__ void __launch_bounds__(256, 1)
attn_kernel() {
    extern __shared__ float sm[];
    float* Ps = sm;
    float* rg = sm + 64 * PST;        // ks/qs region, later B triple-buffer
    float* ks = rg;
    float* qs = rg + 512 * KS_STRIDE;
    const uint32_t ps_u32 = smem_u32(sm);
    const uint32_t rg_u32 = smem_u32(rg);

    const int b    = blockIdx.y;
    const int tile = blockIdx.x;
    const int tid  = threadIdx.x;
    const int qbase = b * TT + tile * 64;

    for (int i = tid; i < TT * DKK; i += 256) {
        int s = i >> 4, d = i & 15;
        ks[s * KS_STRIDE + d] = g_k[(b * TT + s) * DKK + d];
    }
    for (int i = tid; i < 64 * DKK; i += 256)
        qs[i] = g_q[qbase * DKK + i];
    __syncthreads();

    // ---- scores ----
    {
        const int r  = tid >> 2;
        const int tq = tile * 64 + r;
        float qreg[16];
#pragma unroll
        for (int d = 0; d < 16; d++) qreg[d] = qs[r * 16 + d];
        const int s0 = tid & 3;
        for (int j = 0; j < 128; j++) {
            int s = s0 + 4 * j;
            float dot = 0.f;
#pragma unroll
            for (int d = 0; d < 16; d++) dot += qreg[d] * ks[s * KS_STRIDE + d];
            Ps[r * PST + s] = (s > tq) ? NEG_INF : dot * 4.0f;
        }
    }
    __syncthreads();

    // ---- softmax (write P as tf32) ----
    {
        const int w = tid >> 5, l = tid & 31;
        for (int rr = 0; rr < 8; rr++) {
            const int r = w * 8 + rr;
            float v[16];
            float m = -3.4e38f;
#pragma unroll
            for (int i = 0; i < 16; i++) {
                v[i] = Ps[r * PST + l + 32 * i];
                m = fmaxf(m, v[i]);
            }
#pragma unroll
            for (int off = 16; off > 0; off >>= 1)
                m = fmaxf(m, __shfl_xor_sync(0xffffffffu, m, off));
            float ssum = 0.f;
#pragma unroll
            for (int i = 0; i < 16; i++) { v[i] = __expf(v[i] - m); ssum += v[i]; }
#pragma unroll
            for (int off = 16; off > 0; off >>= 1)
                ssum += __shfl_xor_sync(0xffffffffu, ssum, off);
            const float inv = 1.0f / ssum;
#pragma unroll
            for (int i = 0; i < 16; i++)
                Ps[r * PST + l + 32 * i] = to_tf32(v[i] * inv);
        }
    }
    __syncthreads();

    // ---- Y = P @ x  via mma + ldmatrix, 3-stage pipeline ----
    const int wid = tid >> 5, lane = tid & 31;
    const int wm = (wid >> 2) * 32;
    const int wn = (wid & 3) * 32;
    const int lm = lane >> 2, lk = lane & 3;
    const int srow = tid >> 1;
    const int sc4  = (tid & 1) * 4;

    const int lr  = lane & 7;
    const int ah  = (lane >> 3) & 1;
    const int ac  = lane >> 4;
    const uint32_t aAddr0 = ps_u32 + ((wm + ah * 8 + lr) * PST + ac * 4) * 4;
    const uint32_t bAddr0 = rg_u32 + ((wn + lr) * BKP2 + ah * 4) * 4;

    const float* xTb = g_xT + (size_t)b * DD * TT;

#define PREF(ST, BUF) do {                                                           \
        const int _nb = ((ST) >> 4) * 128;                                           \
        const int _k0 = ((ST) & 15) * 32;                                            \
        uint32_t dstb = rg_u32 + ((BUF) * BBUF_FLOATS + srow * BKP2 + sc4 * 4) * 4;  \
        const float* src = xTb + (size_t)(_nb + srow) * TT + _k0 + sc4 * 4;          \
        _Pragma("unroll")                                                            \
        for (int q = 0; q < 4; q++) CP_ASYNC16(dstb + q * 16, src + q * 4);          \
    } while (0)

    float acc[2][4][4];
#pragma unroll
    for (int i = 0; i < 2; i++)
#pragma unroll
        for (int j = 0; j < 4; j++)
#pragma unroll
            for (int r = 0; r < 4; r++) acc[i][j][r] = 0.f;

    PREF(0, 0); CP_COMMIT();
    PREF(1, 1); CP_COMMIT();

    for (int st = 0; st < 128; st++) {
        const int buf = st % 3;
        if (st + 2 < 128) { CP_WAIT(1); } else { CP_WAIT(0); }
        __syncthreads();
        if (st + 2 < 128) { PREF(st + 2, (st + 2) % 3); CP_COMMIT(); }

        const uint32_t bBuf = bAddr0 + buf * BBUF_FLOATS * 4;
        const int kbase = (st & 15) * 32;
#pragma unroll
        for (int ksu = 0; ksu < 4; ksu++) {
            const int kb = kbase + ksu * 8;
            uint32_t a[2][4], bfr[4][2];
#pragma unroll
            for (int mt = 0; mt < 2; mt++)
                LDSM_X4(a[mt][0], a[mt][1], a[mt][2], a[mt][3],
                        aAddr0 + (mt * 16 * PST + kb) * 4);
#pragma unroll
            for (int nt = 0; nt < 4; nt++)
                LDSM_X2(bfr[nt][0], bfr[nt][1],
                        bBuf + (nt * 8 * BKP2 + ksu * 8) * 4);
#pragma unroll
            for (int mt = 0; mt < 2; mt++)
#pragma unroll
                for (int nt = 0; nt < 4; nt++)
                    mma_tf32(acc[mt][nt], a[mt], bfr[nt]);
        }

        if ((st & 15) == 15) {
            const int nb = (st >> 4) * 128;
#pragma unroll
            for (int mt = 0; mt < 2; mt++) {
                const int row = qbase + wm + mt * 16 + lm;
#pragma unroll
                for (int nt = 0; nt < 4; nt++) {
                    const int col = nb + wn + nt * 8 + 2 * lk;
                    float2 v0 = { to_tf32(acc[mt][nt][0]), to_tf32(acc[mt][nt][1]) };
                    float2 v1 = { to_tf32(acc[mt][nt][2]), to_tf32(acc[mt][nt][3]) };
                    *reinterpret_cast<float2*>(g_y + (size_t)row * DD + col) = v0;
                    *reinterpret_cast<float2*>(g_y + (size_t)(row + 8) * DD + col) = v1;
#pragma unroll
                    for (int r = 0; r < 4; r++) acc[mt][nt][r] = 0.f;
                }
            }
        }
    }
#undef PREF
}

// ---------------------------------------------------------------------------
// K3: out = Y @ WvT^T + bv  via mma.sync + ldmatrix, 3-stage pipeline
// ---------------------------------------------------------------------------
#define BM 128
#define BN 128
#define BK 32
#define BKP 36
#define TILE_FLOATS (BM * BKP)
#define GSTAGE_FLOATS (2 * TILE_FLOATS)     // A + B per stage
#define NSTAGE (DD / BK)                    // 32

__global__ void __launch_bounds__(256, 2)
gemm3_mma(const float* __restrict__ bv, float* __restrict__ out) {
    extern __shared__ float sm[];
    const uint32_t sb = smem_u32(sm);

    const int tid  = threadIdx.x;
    const int wid  = tid >> 5, lane = tid & 31;
    const int wm   = (wid >> 2) * 64;
    const int wn   = (wid & 3) * 32;
    const int lm   = lane >> 2, lk = lane & 3;
    const int n0   = blockIdx.x * BN;
    const int m0   = blockIdx.y * BM;

    const float* Arow = g_y   + (size_t)m0 * DD;
    const float* Brow = g_wvT + (size_t)n0 * DD;

    const int srow = tid >> 1;
    const int sc4  = (tid & 1) * 4;

    const int lr = lane & 7;
    const int ah = (lane >> 3) & 1;
    const int ac = lane >> 4;
    const uint32_t aAddr0 = sb + ((wm + ah * 8 + lr) * BKP + ac * 4) * 4;
    const uint32_t bAddr0 = sb + TILE_FLOATS * 4 + ((wn + lr) * BKP + ah * 4) * 4;

#define PREFETCH(S, ST) do {                                                          \
        const int k0 = (S) * BK;                                                      \
        uint32_t abase = sb + ((ST) * GSTAGE_FLOATS + srow * BKP + sc4 * 4) * 4;      \
        uint32_t bbase = abase + TILE_FLOATS * 4;                                     \
        const float* asrc = Arow + (size_t)srow * DD + k0 + sc4 * 4;                  \
        const float* bsrc = Brow + (size_t)srow * DD + k0 + sc4 * 4;                  \
        _Pragma("unroll")                                                             \
        for (int q = 0; q < 4; q++) {                                                 \
            CP_ASYNC16(abase + q * 16, asrc + q * 4);                                 \
            CP_ASYNC16(bbase + q * 16, bsrc + q * 4);                                 \
        }                                                                             \
    } while (0)

    float acc[4][4][4];
#pragma unroll
    for (int i = 0; i < 4; i++)
#pragma unroll
        for (int j = 0; j < 4; j++)
#pragma unroll
            for (int r = 0; r < 4; r++) acc[i][j][r] = 0.f;

    PREFETCH(0, 0); CP_COMMIT();
    PREFETCH(1, 1); CP_COMMIT();

    for (int s = 0; s < NSTAGE; s++) {
        const int st = s % 3;
        if (s + 2 < NSTAGE) { CP_WAIT(1); } else { CP_WAIT(0); }
        __syncthreads();
        if (s + 2 < NSTAGE) { PREFETCH(s + 2, (s + 2) % 3); CP_COMMIT(); }

        const uint32_t aBuf = aAddr0 + st * GSTAGE_FLOATS * 4;
        const uint32_t bBuf = bAddr0 + st * GSTAGE_FLOATS * 4;
#pragma unroll
        for (int ksu = 0; ksu < 4; ksu++) {
            uint32_t a[4][4], b[4][2];
#pragma unroll
            for (int mt = 0; mt < 4; mt++)
                LDSM_X4(a[mt][0], a[mt][1], a[mt][2], a[mt][3],
                        aBuf + (mt * 16 * BKP + ksu * 8) * 4);
#pragma unroll
            for (int nt = 0; nt < 4; nt++)
                LDSM_X2(b[nt][0], b[nt][1],
                        bBuf + (nt * 8 * BKP + ksu * 8) * 4);
#pragma unroll
            for (int mt = 0; mt < 4; mt++)
#pragma unroll
                for (int nt = 0; nt < 4; nt++)
                    mma_tf32(acc[mt][nt], a[mt], b[nt]);
        }
    }
#undef PREFETCH

#pragma unroll
    for (int mt = 0; mt < 4; mt++) {
        const int row = m0 + wm + mt * 16 + lm;
#pragma unroll
        for (int nt = 0; nt < 4; nt++) {
            const int col = n0 + wn + nt * 8 + 2 * lk;
            const float b0 = bv[col], b1 = bv[col + 1];
            float2 v0 = { acc[mt][nt][0] + b0, acc[mt][nt][1] + b1 };
            float2 v1 = { acc[mt][nt][2] + b0, acc[mt][nt][3] + b1 };
            *reinterpret_cast<float2*>(out + (size_t)row * DD + col) = v0;
            *reinterpret_cast<float2*>(out + (size_t)(row + 8) * DD + col) = v1;
        }
    }
}

// ---------------------------------------------------------------------------
extern "C" void kernel_launch(void* const* d_in, const int* in_sizes, int n_in,
                              void* d_out, int out_size) {
    const float*         x    = (const float*)d_in[0];
    const unsigned char* mask = (const unsigned char*)d_in[1];
    const float*         Wq   = (const float*)d_in[2];
    const float*         bq   = (const float*)d_in[3];
    const float*         Wk   = (const float*)d_in[4];
    const float*         bk   = (const float*)d_in[5];
    const float*         Wv   = (const float*)d_in[6];
    const float*         bv   = (const float*)d_in[7];
    float* out = (float*)d_out;

    wvt_kernel<<<dim3(32, 32), dim3(32, 8)>>>(Wv);
    qk_kernel<<<BB * TT / QKR, 256>>>(x, mask, Wq, bq, Wk, bk);

    const size_t asmem = ATT_SMEM_FLOATS * sizeof(float);
    cudaFuncSetAttribute(attn_kernel, cudaFuncAttributeMaxDynamicSharedMemorySize, (int)asmem);
    attn_kernel<<<dim3(TT / 64, BB), 256, asmem>>>();

    const size_t gsmem = 3 * GSTAGE_FLOATS * sizeof(float);   // 110592 B
    cudaFuncSetAttribute(gemm3_mma, cudaFuncAttributeMaxDynamicSharedMemorySize, (int)gsmem);
    gemm3_mma<<<dim3(DD / BN, BB * TT / BM), 256, gsmem>>>(bv, out);
}

// round 10
// speedup vs baseline: 3.6092x; 1.1838x over previous
#include <cuda_runtime.h>
#include <cstdint>

#define BB 64
#define TT 512
#define DD 1024
#define DKK 16
#define NEG_INF (-1e24f)

// scratch (device globals: allocation-free rule)
__device__ float g_q[BB * TT * DKK];
__device__ float g_k[BB * TT * DKK];
__device__ float g_y[(size_t)BB * TT * DD];
__device__ float g_wvT[DD * DD];
__device__ float g_xT[(size_t)BB * DD * TT];   // per-batch x^T, tf32-rounded

// ---------------------------------------------------------------------------
// helpers
// ---------------------------------------------------------------------------
__device__ __forceinline__ uint32_t smem_u32(const void* p) {
    uint32_t a;
    asm("{ .reg .u64 t; cvta.to.shared.u64 t, %1; cvt.u32.u64 %0, t; }"
        : "=r"(a) : "l"(p));
    return a;
}
__device__ __forceinline__ float to_tf32(float x) {
    uint32_t r;
    asm("cvt.rna.tf32.f32 %0, %1;" : "=r"(r) : "f"(x));
    return __uint_as_float(r);
}

#define CP_ASYNC16(dst_u32, src_ptr) \
    asm volatile("cp.async.cg.shared.global [%0], [%1], 16;" \
                 :: "r"(dst_u32), "l"(src_ptr) : "memory")
#define CP_COMMIT() asm volatile("cp.async.commit_group;" ::: "memory")
#define CP_WAIT(n)  asm volatile("cp.async.wait_group %0;" :: "n"(n) : "memory")

__device__ __forceinline__ void mma_tf32(float* d, const uint32_t* a, const uint32_t* b) {
    asm volatile(
        "mma.sync.aligned.m16n8k8.row.col.f32.tf32.tf32.f32 "
        "{%0,%1,%2,%3}, {%4,%5,%6,%7}, {%8,%9}, {%0,%1,%2,%3};"
        : "+f"(d[0]), "+f"(d[1]), "+f"(d[2]), "+f"(d[3])
        : "r"(a[0]), "r"(a[1]), "r"(a[2]), "r"(a[3]), "r"(b[0]), "r"(b[1]));
}

// ldmatrix: 8x8 b16 matrices == 8x4 fp32 tiles; lane -> (row l>>2, f32col l&3)
#define LDSM_X4(r0, r1, r2, r3, addr) \
    asm volatile("ldmatrix.sync.aligned.m8n8.x4.shared.b16 {%0,%1,%2,%3}, [%4];" \
                 : "=r"(r0), "=r"(r1), "=r"(r2), "=r"(r3) : "r"(addr))

// ---------------------------------------------------------------------------
// K0: WvT[n][k] = tf32(Wv[k][n])
// ---------------------------------------------------------------------------
__global__ void wvt_kernel(const float* __restrict__ Wv) {
    __shared__ float t[32][33];
    const int bx = blockIdx.x * 32, by = blockIdx.y * 32;
    const int tx = threadIdx.x, ty = threadIdx.y;
#pragma unroll
    for (int i = 0; i < 32; i += 8)
        t[ty + i][tx] = Wv[(size_t)(by + ty + i) * DD + bx + tx];
    __syncthreads();
#pragma unroll
    for (int i = 0; i < 32; i += 8)
        g_wvT[(size_t)(bx + ty + i) * DD + by + tx] = to_tf32(t[tx][ty + i]);
}

// ---------------------------------------------------------------------------
// K1: smem-GEMM qk + fused xT emission (unchanged from round 9)
// ---------------------------------------------------------------------------
#define QKR 128
#define QKC 64
#define QKPAD 68

__global__ void __launch_bounds__(256, 2)
qk_kernel(const float* __restrict__ x,
          const unsigned char* __restrict__ maskb,
          const float* __restrict__ Wq, const float* __restrict__ bq,
          const float* __restrict__ Wk, const float* __restrict__ bk) {
    __shared__ float xs[QKR * QKPAD];
    __shared__ float ws[QKC * 32];
    const uint32_t xs_u32 = smem_u32(xs);
    const uint32_t ws_u32 = smem_u32(ws);

    const int tid = threadIdx.x;
    const int r0  = blockIdx.x * QKR;
    const int b   = r0 / TT;
    const int sl0 = r0 % TT;

    const int tr = tid >> 3, tc = tid & 7;

    float acc[4][4];
#pragma unroll
    for (int j = 0; j < 4; j++) {
        const int c = tc * 4 + j;
        const float bias = (c < 16) ? bq[c] : bk[c - 16];
#pragma unroll
        for (int i = 0; i < 4; i++) acc[i][j] = bias;
    }

    const int ed   = tid >> 2;
    const int eseg = (tid & 3) * 32;

    for (int ch = 0; ch < 16; ch++) {
        const int k0 = ch * QKC;
        {
            const int kk = tid >> 2, c4 = tid & 3;
            CP_ASYNC16(ws_u32 + (kk * 32 + c4 * 4) * 4,
                       Wq + (size_t)(k0 + kk) * DKK + c4 * 4);
            CP_ASYNC16(ws_u32 + (kk * 32 + 16 + c4 * 4) * 4,
                       Wk + (size_t)(k0 + kk) * DKK + c4 * 4);
        }
#pragma unroll
        for (int it = 0; it < 8; it++) {
            const int idx = tid + it * 256;
            const int row = idx >> 4, c4 = idx & 15;
            CP_ASYNC16(xs_u32 + (row * QKPAD + c4 * 4) * 4,
                       x + (size_t)(r0 + row) * DD + k0 + c4 * 4);
        }
        CP_COMMIT();
        CP_WAIT(0);
        __syncthreads();

#pragma unroll 4
        for (int kk = 0; kk < QKC; kk++) {
            float a[4];
#pragma unroll
            for (int i = 0; i < 4; i++) a[i] = xs[(tr * 4 + i) * QKPAD + kk];
            const float4 w = *reinterpret_cast<const float4*>(&ws[kk * 32 + tc * 4]);
#pragma unroll
            for (int i = 0; i < 4; i++) {
                acc[i][0] += a[i] * w.x;
                acc[i][1] += a[i] * w.y;
                acc[i][2] += a[i] * w.z;
                acc[i][3] += a[i] * w.w;
            }
        }

        {
            float* dst = g_xT + (size_t)b * DD * TT + (size_t)(k0 + ed) * TT + sl0 + eseg;
#pragma unroll
            for (int j = 0; j < 8; j++) {
                float4 v;
                v.x = to_tf32(xs[(eseg + 4 * j + 0) * QKPAD + ed]);
                v.y = to_tf32(xs[(eseg + 4 * j + 1) * QKPAD + ed]);
                v.z = to_tf32(xs[(eseg + 4 * j + 2) * QKPAD + ed]);
                v.w = to_tf32(xs[(eseg + 4 * j + 3) * QKPAD + ed]);
                *reinterpret_cast<float4*>(dst + 4 * j) = v;
            }
        }
        __syncthreads();
    }

    int nz = 0;
#pragma unroll
    for (int p = 0; p < 64; p++)
        if (p & 3) nz |= maskb[p];
    const bool isBool = (nz != 0);

#pragma unroll
    for (int i = 0; i < 4; i++) {
        const int row = r0 + tr * 4 + i;
        const int mv = isBool ? (int)maskb[row]
                              : reinterpret_cast<const int*>(maskb)[row];
#pragma unroll
        for (int j = 0; j < 4; j++) {
            const int c = tc * 4 + j;
            if (c < 16) g_q[row * DKK + c] = acc[i][j];
            else        g_k[row * DKK + (c - 16)] = mv ? NEG_INF : acc[i][j];
        }
    }
}

// ---------------------------------------------------------------------------
// K2: scores + softmax + Y = P@x, with EXACT causal skip (pathology flag)
// ---------------------------------------------------------------------------
#define PST 516
#define KS_STRIDE 17
#define BKP2 36
#define BBUF_FLOATS (128 * BKP2)                      // 4608
#define REGION_FLOATS (3 * BBUF_FLOATS)               // 13824
#define ATT_SMEM_FLOATS (64 * PST + REGION_FLOATS)    // 46848

__global__ void __launch_bounds__(256, 1)
attn_kernel() {
    extern __shared__ float sm[];
    __shared__ int s_flag;
    float* Ps = sm;
    float* rg = sm + 64 * PST;
    float* ks = rg;
    float* qs = rg + 512 * KS_STRIDE;
    const uint32_t ps_u32 = smem_u32(sm);
    const uint32_t rg_u32 = smem_u32(rg);

    const int b    = blockIdx.y;
    const int tile = blockIdx.x;
    const int tid  = threadIdx.x;
    const int qbase = b * TT + tile * 64;

    if (tid == 0) s_flag = 0;
    for (int i = tid; i < TT * DKK; i += 256) {
        int s = i >> 4, d = i & 15;
        ks[s * KS_STRIDE + d] = g_k[(b * TT + s) * DKK + d];
    }
    for (int i = tid; i < 64 * DKK; i += 256)
        qs[i] = g_q[qbase * DKK + i];
    __syncthreads();

    // ---- scores (only s < 64*(tile+1) computed; tail set to NEG_INF) ----
    {
        const int r  = tid >> 2;
        const int tq = tile * 64 + r;
        float qreg[16];
#pragma unroll
        for (int d = 0; d < 16; d++) qreg[d] = qs[r * 16 + d];
        const int s0 = tid & 3;
        const int jmax = 16 * (tile + 1);
        for (int j = 0; j < jmax; j++) {
            int s = s0 + 4 * j;
            float dot = 0.f;
#pragma unroll
            for (int d = 0; d < 16; d++) dot += qreg[d] * ks[s * KS_STRIDE + d];
            Ps[r * PST + s] = (s > tq) ? NEG_INF : dot * 4.0f;
        }
        for (int j = jmax; j < 128; j++)
            Ps[r * PST + s0 + 4 * j] = NEG_INF;
    }
    __syncthreads();

    // ---- softmax (write P as tf32); detect pathological rows ----
    {
        const int w = tid >> 5, l = tid & 31;
        for (int rr = 0; rr < 8; rr++) {
            const int r = w * 8 + rr;
            float v[16];
            float m = -3.4e38f;
#pragma unroll
            for (int i = 0; i < 16; i++) {
                v[i] = Ps[r * PST + l + 32 * i];
                m = fmaxf(m, v[i]);
            }
#pragma unroll
            for (int off = 16; off > 0; off >>= 1)
                m = fmaxf(m, __shfl_xor_sync(0xffffffffu, m, off));
            // pathological: row max is the causal -1e24 (mass escapes the
            // causal window) -> this CTA must reduce over all 512 keys
            if (l == 0 && m < -1e20f) s_flag = 1;
            float ssum = 0.f;
#pragma unroll
            for (int i = 0; i < 16; i++) { v[i] = __expf(v[i] - m); ssum += v[i]; }
#pragma unroll
            for (int off = 16; off > 0; off >>= 1)
                ssum += __shfl_xor_sync(0xffffffffu, ssum, off);
            const float inv = 1.0f / ssum;
#pragma unroll
            for (int i = 0; i < 16; i++)
                Ps[r * PST + l + 32 * i] = to_tf32(v[i] * inv);
        }
    }
    __syncthreads();

    // ---- Y = P @ x via mma + ldmatrix, 3-stage, causal chunk skip ----
    const int wid = tid >> 5, lane = tid & 31;
    const int wm = (wid >> 2) * 32;
    const int wn = (wid & 3) * 32;
    const int lm = lane >> 2, lk = lane & 3;
    const int srow = tid >> 1;
    const int sc4  = (tid & 1) * 4;

    const int lr  = lane & 7;
    const int ah  = (lane >> 3) & 1;
    const int ac  = lane >> 4;
    const uint32_t aAddr0 = ps_u32 + ((wm + ah * 8 + lr) * PST + ac * 4) * 4;
    // B x4 address: matrices (nt,k0-3),(nt,k4-7),(nt+1,k0-3),(nt+1,k4-7)
    const uint32_t bAddrX4 = rg_u32 +
        ((wn + ((lane >> 4) & 1) * 8 + lr) * BKP2 + ((lane >> 3) & 1) * 4) * 4;

    const float* xTb = g_xT + (size_t)b * DD * TT;

    const int nch = s_flag ? 16 : 2 * (tile + 1);   // k-chunks per nb
    const int tot = 8 * nch;

#define PREF2(NB, KC, BUF) do {                                                      \
        uint32_t dstb = rg_u32 + ((BUF) * BBUF_FLOATS + srow * BKP2 + sc4 * 4) * 4;  \
        const float* src = xTb + (size_t)((NB) * 128 + srow) * TT + (KC) * 32 + sc4 * 4; \
        _Pragma("unroll")                                                            \
        for (int q = 0; q < 4; q++) CP_ASYNC16(dstb + q * 16, src + q * 4);          \
    } while (0)

    float acc[2][4][4];
#pragma unroll
    for (int i = 0; i < 2; i++)
#pragma unroll
        for (int j = 0; j < 4; j++)
#pragma unroll
            for (int r = 0; r < 4; r++) acc[i][j][r] = 0.f;

    int nbP = 0, kcP = 0;
    PREF2(nbP, kcP, 0); CP_COMMIT();
    if (++kcP == nch) { kcP = 0; nbP++; }
    PREF2(nbP, kcP, 1); CP_COMMIT();
    if (++kcP == nch) { kcP = 0; nbP++; }

    int nbC = 0, kcC = 0;
    for (int st = 0; st < tot; st++) {
        const int buf = st % 3;
        if (st + 2 < tot) { CP_WAIT(1); } else { CP_WAIT(0); }
        __syncthreads();
        if (st + 2 < tot) {
            PREF2(nbP, kcP, (st + 2) % 3); CP_COMMIT();
            if (++kcP == nch) { kcP = 0; nbP++; }
        }

        const uint32_t bBuf = bAddrX4 + buf * BBUF_FLOATS * 4;
        const int kbase = kcC * 32;
#pragma unroll
        for (int ksu = 0; ksu < 4; ksu++) {
            const int kb = kbase + ksu * 8;
            uint32_t a[2][4], bfr[4][2];
#pragma unroll
            for (int mt = 0; mt < 2; mt++)
                LDSM_X4(a[mt][0], a[mt][1], a[mt][2], a[mt][3],
                        aAddr0 + (mt * 16 * PST + kb) * 4);
#pragma unroll
            for (int p = 0; p < 2; p++)
                LDSM_X4(bfr[2 * p][0], bfr[2 * p][1], bfr[2 * p + 1][0], bfr[2 * p + 1][1],
                        bBuf + (p * 16 * BKP2 + ksu * 8) * 4);
#pragma unroll
            for (int mt = 0; mt < 2; mt++)
#pragma unroll
                for (int nt = 0; nt < 4; nt++)
                    mma_tf32(acc[mt][nt], a[mt], bfr[nt]);
        }

        if (kcC == nch - 1) {
            const int nb = nbC * 128;
#pragma unroll
            for (int mt = 0; mt < 2; mt++) {
                const int row = qbase + wm + mt * 16 + lm;
#pragma unroll
                for (int nt = 0; nt < 4; nt++) {
                    const int col = nb + wn + nt * 8 + 2 * lk;
                    float2 v0 = { to_tf32(acc[mt][nt][0]), to_tf32(acc[mt][nt][1]) };
                    float2 v1 = { to_tf32(acc[mt][nt][2]), to_tf32(acc[mt][nt][3]) };
                    *reinterpret_cast<float2*>(g_y + (size_t)row * DD + col) = v0;
                    *reinterpret_cast<float2*>(g_y + (size_t)(row + 8) * DD + col) = v1;
#pragma unroll
                    for (int r = 0; r < 4; r++) acc[mt][nt][r] = 0.f;
                }
            }
        }
        if (++kcC == nch) { kcC = 0; nbC++; }
    }
#undef PREF2
}

// ---------------------------------------------------------------------------
// K3: out = Y @ WvT^T + bv  via mma.sync + ldmatrix, 3-stage pipeline
// ---------------------------------------------------------------------------
#define BM 128
#define BN 128
#define BK 32
#define BKP 36
#define TILE_FLOATS (BM * BKP)
#define GSTAGE_FLOATS (2 * TILE_FLOATS)
#define NSTAGE (DD / BK)

__global__ void __launch_bounds__(256, 2)
gemm3_mma(const float* __restrict__ bv, float* __restrict__ out) {
    extern __shared__ float sm[];
    const uint32_t sb = smem_u32(sm);

    const int tid  = threadIdx.x;
    const int wid  = tid >> 5, lane = tid & 31;
    const int wm   = (wid >> 2) * 64;
    const int wn   = (wid & 3) * 32;
    const int lm   = lane >> 2, lk = lane & 3;
    const int n0   = blockIdx.x * BN;
    const int m0   = blockIdx.y * BM;

    const float* Arow = g_y   + (size_t)m0 * DD;
    const float* Brow = g_wvT + (size_t)n0 * DD;

    const int srow = tid >> 1;
    const int sc4  = (tid & 1) * 4;

    const int lr = lane & 7;
    const int ah = (lane >> 3) & 1;
    const int ac = lane >> 4;
    const uint32_t aAddr0 = sb + ((wm + ah * 8 + lr) * BKP + ac * 4) * 4;
    const uint32_t bAddrX4 = sb + TILE_FLOATS * 4 +
        ((wn + ((lane >> 4) & 1) * 8 + lr) * BKP + ((lane >> 3) & 1) * 4) * 4;

#define PREFETCH(S, ST) do {                                                          \
        const int k0 = (S) * BK;                                                      \
        uint32_t abase = sb + ((ST) * GSTAGE_FLOATS + srow * BKP + sc4 * 4) * 4;      \
        uint32_t bbase = abase + TILE_FLOATS * 4;                                     \
        const float* asrc = Arow + (size_t)srow * DD + k0 + sc4 * 4;                  \
        const float* bsrc = Brow + (size_t)srow * DD + k0 + sc4 * 4;                  \
        _Pragma("unroll")                                                             \
        for (int q = 0; q < 4; q++) {                                                 \
            CP_ASYNC16(abase + q * 16, asrc + q * 4);                                 \
            CP_ASYNC16(bbase + q * 16, bsrc + q * 4);                                 \
        }                                                                             \
    } while (0)

    float acc[4][4][4];
#pragma unroll
    for (int i = 0; i < 4; i++)
#pragma unroll
        for (int j = 0; j < 4; j++)
#pragma unroll
            for (int r = 0; r < 4; r++) acc[i][j][r] = 0.f;

    PREFETCH(0, 0); CP_COMMIT();
    PREFETCH(1, 1); CP_COMMIT();

    for (int s = 0; s < NSTAGE; s++) {
        const int st = s % 3;
        if (s + 2 < NSTAGE) { CP_WAIT(1); } else { CP_WAIT(0); }
        __syncthreads();
        if (s + 2 < NSTAGE) { PREFETCH(s + 2, (s + 2) % 3); CP_COMMIT(); }

        const uint32_t aBuf = aAddr0 + st * GSTAGE_FLOATS * 4;
        const uint32_t bBuf = bAddrX4 + st * GSTAGE_FLOATS * 4;
#pragma unroll
        for (int ksu = 0; ksu < 4; ksu++) {
            uint32_t a[4][4], b[4][2];
#pragma unroll
            for (int mt = 0; mt < 4; mt++)
                LDSM_X4(a[mt][0], a[mt][1], a[mt][2], a[mt][3],
                        aBuf + (mt * 16 * BKP + ksu * 8) * 4);
#pragma unroll
            for (int p = 0; p < 2; p++)
                LDSM_X4(b[2 * p][0], b[2 * p][1], b[2 * p + 1][0], b[2 * p + 1][1],
                        bBuf + (p * 16 * BKP + ksu * 8) * 4);
#pragma unroll
            for (int mt = 0; mt < 4; mt++)
#pragma unroll
                for (int nt = 0; nt < 4; nt++)
                    mma_tf32(acc[mt][nt], a[mt], b[nt]);
        }
    }
#undef PREFETCH

#pragma unroll
    for (int mt = 0; mt < 4; mt++) {
        const int row = m0 + wm + mt * 16 + lm;
#pragma unroll
        for (int nt = 0; nt < 4; nt++) {
            const int col = n0 + wn + nt * 8 + 2 * lk;
            const float b0 = bv[col], b1 = bv[col + 1];
            float2 v0 = { acc[mt][nt][0] + b0, acc[mt][nt][1] + b1 };
            float2 v1 = { acc[mt][nt][2] + b0, acc[mt][nt][3] + b1 };
            *reinterpret_cast<float2*>(out + (size_t)row * DD + col) = v0;
            *reinterpret_cast<float2*>(out + (size_t)(row + 8) * DD + col) = v1;
        }
    }
}

// ---------------------------------------------------------------------------
extern "C" void kernel_launch(void* const* d_in, const int* in_sizes, int n_in,
                              void* d_out, int out_size) {
    const float*         x    = (const float*)d_in[0];
    const unsigned char* mask = (const unsigned char*)d_in[1];
    const float*         Wq   = (const float*)d_in[2];
    const float*         bq   = (const float*)d_in[3];
    const float*         Wk   = (const float*)d_in[4];
    const float*         bk   = (const float*)d_in[5];
    const float*         Wv   = (const float*)d_in[6];
    const float*         bv   = (const float*)d_in[7];
    float* out = (float*)d_out;

    wvt_kernel<<<dim3(32, 32), dim3(32, 8)>>>(Wv);
    qk_kernel<<<BB * TT / QKR, 256>>>(x, mask, Wq, bq, Wk, bk);

    const size_t asmem = ATT_SMEM_FLOATS * sizeof(float);
    cudaFuncSetAttribute(attn_kernel, cudaFuncAttributeMaxDynamicSharedMemorySize, (int)asmem);
    attn_kernel<<<dim3(TT / 64, BB), 256, asmem>>>();

    const size_t gsmem = 3 * GSTAGE_FLOATS * sizeof(float);
    cudaFuncSetAttribute(gemm3_mma, cudaFuncAttributeMaxDynamicSharedMemorySize, (int)gsmem);
    gemm3_mma<<<dim3(DD / BN, BB * TT / BM), 256, gsmem>>>(bv, out);
}